// round 1
// baseline (speedup 1.0000x reference)
#include <cuda_runtime.h>

#define B_   4
#define S_   2048
#define F_   64
#define HID_ 256
#define D_   128
#define H_   8
#define DK_  16

#define TOK  32     // tokens per MLP block
#define QT   128    // queries per attention block
#define CH   128    // keys per smem chunk

// Scratch: q/k/v in head-major layout [B*H, S, DK]  (4 MB each)
__device__ float    g_q[B_ * H_ * S_ * DK_];
__device__ float    g_k[B_ * H_ * S_ * DK_];
__device__ float    g_v[B_ * H_ * S_ * DK_];
__device__ unsigned g_max[B_ * D_];

// ---- order-preserving float <-> uint keys for atomicMax ----
__device__ __forceinline__ unsigned fkey(float f) {
    unsigned u = __float_as_uint(f);
    return (u & 0x80000000u) ? ~u : (u | 0x80000000u);
}
__device__ __forceinline__ float ikey(unsigned k) {
    unsigned u = (k & 0x80000000u) ? (k & 0x7FFFFFFFu) : ~k;
    return __uint_as_float(u);
}

__global__ void init_kernel() {
    g_max[threadIdx.x] = 0u;   // below every real key
}

// ============================================================
// Fused 2-layer MLP: one block = 32 tokens, blockIdx.y selects q/k/v.
// Writes output in head-major layout for the attention kernel.
// ============================================================
__global__ void __launch_bounds__(256) qkv_mlp_kernel(
    const float* __restrict__ x,
    const float* __restrict__ qW1, const float* __restrict__ qb1,
    const float* __restrict__ qW2, const float* __restrict__ qb2,
    const float* __restrict__ kW1, const float* __restrict__ kb1,
    const float* __restrict__ kW2, const float* __restrict__ kb2,
    const float* __restrict__ vW1, const float* __restrict__ vb1,
    const float* __restrict__ vW2, const float* __restrict__ vb2)
{
    const int tid = threadIdx.x;
    const int mlp = blockIdx.y;

    const float *W1, *b1, *W2, *b2;
    float* outg;
    if (mlp == 0)      { W1 = qW1; b1 = qb1; W2 = qW2; b2 = qb2; outg = g_q; }
    else if (mlp == 1) { W1 = kW1; b1 = kb1; W2 = kW2; b2 = kb2; outg = g_k; }
    else               { W1 = vW1; b1 = vb1; W2 = vW2; b2 = vb2; outg = g_v; }

    const int tok0 = blockIdx.x * TOK;

    __shared__ float xs[TOK][F_];      // 8 KB
    __shared__ float hs[TOK][HID_];    // 32 KB

    // Load x tile: 32*64 = 2048 floats = 512 float4; 2 per thread.
    {
        const float4* xg  = (const float4*)(x + tok0 * F_);
        float4*       xs4 = (float4*)&xs[0][0];
        xs4[tid]       = xg[tid];
        xs4[tid + 256] = xg[tid + 256];
    }
    __syncthreads();

    // ---- Phase 1: hidden = elu(x @ W1 + b1); thread = hidden channel j=tid
    {
        float acc[TOK];
        #pragma unroll
        for (int t = 0; t < TOK; t++) acc[t] = 0.f;

        for (int i = 0; i < F_; i += 4) {
            const float w0 = W1[(i + 0) * HID_ + tid];
            const float w1 = W1[(i + 1) * HID_ + tid];
            const float w2 = W1[(i + 2) * HID_ + tid];
            const float w3 = W1[(i + 3) * HID_ + tid];
            #pragma unroll
            for (int t = 0; t < TOK; t++) {
                const float4 xv = *(const float4*)&xs[t][i];
                float a = acc[t];
                a = fmaf(xv.x, w0, a);
                a = fmaf(xv.y, w1, a);
                a = fmaf(xv.z, w2, a);
                a = fmaf(xv.w, w3, a);
                acc[t] = a;
            }
        }
        const float bb = b1[tid];
        #pragma unroll
        for (int t = 0; t < TOK; t++) {
            float h = acc[t] + bb;
            hs[t][tid] = (h > 0.f) ? h : (expf(h) - 1.f);
        }
    }
    __syncthreads();

    // ---- Phase 2: out = hidden @ W2 + b2; thread = (out channel j, half of tokens)
    {
        const int j  = tid & 127;     // 0..127
        const int tg = tid >> 7;      // 0/1 -> tokens [tg*16, tg*16+16)
        float acc[16];
        #pragma unroll
        for (int t = 0; t < 16; t++) acc[t] = 0.f;

        for (int i = 0; i < HID_; i += 4) {
            const float w0 = W2[(i + 0) * D_ + j];
            const float w1 = W2[(i + 1) * D_ + j];
            const float w2 = W2[(i + 2) * D_ + j];
            const float w3 = W2[(i + 3) * D_ + j];
            #pragma unroll
            for (int t = 0; t < 16; t++) {
                const float4 hv = *(const float4*)&hs[tg * 16 + t][i];
                float a = acc[t];
                a = fmaf(hv.x, w0, a);
                a = fmaf(hv.y, w1, a);
                a = fmaf(hv.z, w2, a);
                a = fmaf(hv.w, w3, a);
                acc[t] = a;
            }
        }
        const float bb = b2[j];
        const int h  = j >> 4;
        const int dk = j & 15;
        #pragma unroll
        for (int t = 0; t < 16; t++) {
            const int tok = tok0 + tg * 16 + t;
            const int b   = tok >> 11;          // / S_
            const int s   = tok & (S_ - 1);
            outg[((b * H_ + h) * S_ + s) * DK_ + dk] = acc[t] + bb;
        }
    }
}

// ============================================================
// Flash-style attention + column-max reduction.
// grid (S/QT, B*H), 128 threads, one thread per query.
// ============================================================
__global__ void __launch_bounds__(128) attn_kernel()
{
    const int tid = threadIdx.x;
    const int bh  = blockIdx.y;                  // 0..31
    const int qi  = blockIdx.x * QT + tid;

    // Load q, pre-scale by 1/sqrt(DK) = 0.25
    float q[DK_];
    {
        const float4* qp = (const float4*)(g_q + (bh * S_ + qi) * DK_);
        #pragma unroll
        for (int u = 0; u < 4; u++) {
            float4 t4 = qp[u];
            q[u * 4 + 0] = t4.x * 0.25f;
            q[u * 4 + 1] = t4.y * 0.25f;
            q[u * 4 + 2] = t4.z * 0.25f;
            q[u * 4 + 3] = t4.w * 0.25f;
        }
    }

    __shared__ float4 ks[CH][4];                 // 8 KB
    __shared__ float4 vs[CH][4];                 // 8 KB
    __shared__ float  red[QT][DK_ + 1];          // 8.5 KB, padded vs bank conflicts

    float m = -1e30f, l = 0.f;
    float acc[DK_];
    #pragma unroll
    for (int d = 0; d < DK_; d++) acc[d] = 0.f;

    const float4* kg = (const float4*)(g_k + bh * S_ * DK_);
    const float4* vg = (const float4*)(g_v + bh * S_ * DK_);

    for (int c = 0; c < S_; c += CH) {
        __syncthreads();
        #pragma unroll
        for (int u = 0; u < 4; u++) {
            ks[tid][u] = kg[(c + tid) * 4 + u];
            vs[tid][u] = vg[(c + tid) * 4 + u];
        }
        __syncthreads();

        #pragma unroll 4
        for (int jj = 0; jj < CH; jj++) {
            const float4 k0 = ks[jj][0], k1 = ks[jj][1];
            const float4 k2 = ks[jj][2], k3 = ks[jj][3];
            // tree-reduced dot product (q already scaled)
            float s0 = fmaf(q[1],  k0.y, q[0]  * k0.x);
            float s1 = fmaf(q[3],  k0.w, q[2]  * k0.z);
            float s2 = fmaf(q[5],  k1.y, q[4]  * k1.x);
            float s3 = fmaf(q[7],  k1.w, q[6]  * k1.z);
            float s4 = fmaf(q[9],  k2.y, q[8]  * k2.x);
            float s5 = fmaf(q[11], k2.w, q[10] * k2.z);
            float s6 = fmaf(q[13], k3.y, q[12] * k3.x);
            float s7 = fmaf(q[15], k3.w, q[14] * k3.z);
            const float sc = ((s0 + s1) + (s2 + s3)) + ((s4 + s5) + (s6 + s7));

            if (sc > m) {
                const float alpha = __expf(m - sc);
                m = sc;
                l *= alpha;
                #pragma unroll
                for (int d = 0; d < DK_; d++) acc[d] *= alpha;
            }
            const float p = __expf(sc - m);
            l += p;

            const float4 v0 = vs[jj][0], v1 = vs[jj][1];
            const float4 v2 = vs[jj][2], v3 = vs[jj][3];
            acc[0]  = fmaf(p, v0.x, acc[0]);
            acc[1]  = fmaf(p, v0.y, acc[1]);
            acc[2]  = fmaf(p, v0.z, acc[2]);
            acc[3]  = fmaf(p, v0.w, acc[3]);
            acc[4]  = fmaf(p, v1.x, acc[4]);
            acc[5]  = fmaf(p, v1.y, acc[5]);
            acc[6]  = fmaf(p, v1.z, acc[6]);
            acc[7]  = fmaf(p, v1.w, acc[7]);
            acc[8]  = fmaf(p, v2.x, acc[8]);
            acc[9]  = fmaf(p, v2.y, acc[9]);
            acc[10] = fmaf(p, v2.z, acc[10]);
            acc[11] = fmaf(p, v2.w, acc[11]);
            acc[12] = fmaf(p, v3.x, acc[12]);
            acc[13] = fmaf(p, v3.y, acc[13]);
            acc[14] = fmaf(p, v3.z, acc[14]);
            acc[15] = fmaf(p, v3.w, acc[15]);
        }
    }

    // normalize + block max-reduce over the 128 queries
    const float inv = 1.f / l;
    #pragma unroll
    for (int d = 0; d < DK_; d++) red[tid][d] = acc[d] * inv;
    __syncthreads();

    for (int off = 64; off > 0; off >>= 1) {
        if (tid < off) {
            #pragma unroll
            for (int d = 0; d < DK_; d++)
                red[tid][d] = fmaxf(red[tid][d], red[tid + off][d]);
        }
        __syncthreads();
    }

    if (tid < DK_) {
        const int b = bh >> 3, h = bh & 7;
        atomicMax(&g_max[b * D_ + h * DK_ + tid], fkey(red[0][tid]));
    }
}

__global__ void finalize_kernel(float* __restrict__ out) {
    out[threadIdx.x] = ikey(g_max[threadIdx.x]);
}

extern "C" void kernel_launch(void* const* d_in, const int* in_sizes, int n_in,
                              void* d_out, int out_size)
{
    const float* x   = (const float*)d_in[0];
    const float* qW1 = (const float*)d_in[1];
    const float* qb1 = (const float*)d_in[2];
    const float* qW2 = (const float*)d_in[3];
    const float* qb2 = (const float*)d_in[4];
    const float* kW1 = (const float*)d_in[5];
    const float* kb1 = (const float*)d_in[6];
    const float* kW2 = (const float*)d_in[7];
    const float* kb2 = (const float*)d_in[8];
    const float* vW1 = (const float*)d_in[9];
    const float* vb1 = (const float*)d_in[10];
    const float* vW2 = (const float*)d_in[11];
    const float* vb2 = (const float*)d_in[12];

    init_kernel<<<1, B_ * D_>>>();

    dim3 gmlp(B_ * S_ / TOK, 3);
    qkv_mlp_kernel<<<gmlp, 256>>>(x, qW1, qb1, qW2, qb2,
                                     kW1, kb1, kW2, kb2,
                                     vW1, vb1, vW2, vb2);

    dim3 gatt(S_ / QT, B_ * H_);
    attn_kernel<<<gatt, QT>>>();

    finalize_kernel<<<1, B_ * D_>>>((float*)d_out);
}

// round 2
// speedup vs baseline: 1.0561x; 1.0561x over previous
#include <cuda_runtime.h>

#define B_   4
#define S_   2048
#define F_   64
#define HID_ 256
#define D_   128
#define H_   8
#define DK_  16

#define TOK  32      // tokens per MLP block
#define XSTR 36      // padded token stride (floats): 16B-aligned rows, few bank conflicts
#define QT   256     // queries per attention block (2 per thread, 128 threads)
#define CH   128     // keys per smem chunk
#define KSTR 36      // floats per key-pair row in ksm (32 data + 4 pad, 144B aligned)
#define VSTR 20      // floats per key row in vsm (16 data + 4 pad, 80B aligned)

// Scratch: q/k/v in head-major layout [B*H, S, DK]
__device__ float    g_q[B_ * H_ * S_ * DK_];
__device__ float    g_k[B_ * H_ * S_ * DK_];
__device__ float    g_v[B_ * H_ * S_ * DK_];
__device__ unsigned g_max[B_ * D_];

// ---- packed f32x2 helpers ----
typedef unsigned long long u64;

__device__ __forceinline__ u64 pk2(float lo, float hi) {
    u64 r;
    asm("mov.b64 %0, {%1, %2};" : "=l"(r) : "r"(__float_as_uint(lo)), "r"(__float_as_uint(hi)));
    return r;
}
__device__ __forceinline__ void upk2(u64 v, float& lo, float& hi) {
    unsigned a, b;
    asm("mov.b64 {%0, %1}, %2;" : "=r"(a), "=r"(b) : "l"(v));
    lo = __uint_as_float(a);
    hi = __uint_as_float(b);
}
__device__ __forceinline__ u64 fma2(u64 a, u64 b, u64 c) {
    u64 d;
    asm("fma.rn.f32x2 %0, %1, %2, %3;" : "=l"(d) : "l"(a), "l"(b), "l"(c));
    return d;
}
__device__ __forceinline__ u64 add2(u64 a, u64 b) {
    u64 d;
    asm("add.rn.f32x2 %0, %1, %2;" : "=l"(d) : "l"(a), "l"(b));
    return d;
}
__device__ __forceinline__ u64 mul2(u64 a, u64 b) {
    u64 d;
    asm("mul.rn.f32x2 %0, %1, %2;" : "=l"(d) : "l"(a), "l"(b));
    return d;
}

// ---- order-preserving float <-> uint keys for atomicMax ----
__device__ __forceinline__ unsigned fkey(float f) {
    unsigned u = __float_as_uint(f);
    return (u & 0x80000000u) ? ~u : (u | 0x80000000u);
}
__device__ __forceinline__ float ikey(unsigned k) {
    unsigned u = (k & 0x80000000u) ? (k & 0x7FFFFFFFu) : ~k;
    return __uint_as_float(u);
}

__global__ void init_kernel() {
    g_max[threadIdx.x] = 0u;
}

// ============================================================
// Fused 2-layer MLP, f32x2-packed across token pairs.
// One block = 32 tokens; blockIdx.y selects q/k/v MLP.
// ============================================================
__global__ void __launch_bounds__(256) qkv_mlp_kernel(
    const float* __restrict__ x,
    const float* __restrict__ qW1, const float* __restrict__ qb1,
    const float* __restrict__ qW2, const float* __restrict__ qb2,
    const float* __restrict__ kW1, const float* __restrict__ kb1,
    const float* __restrict__ kW2, const float* __restrict__ kb2,
    const float* __restrict__ vW1, const float* __restrict__ vb1,
    const float* __restrict__ vW2, const float* __restrict__ vb2)
{
    const int tid = threadIdx.x;
    const int mlp = blockIdx.y;

    const float *W1, *b1, *W2, *b2;
    float* outg;
    if (mlp == 0)      { W1 = qW1; b1 = qb1; W2 = qW2; b2 = qb2; outg = g_q; }
    else if (mlp == 1) { W1 = kW1; b1 = kb1; W2 = kW2; b2 = kb2; outg = g_k; }
    else               { W1 = vW1; b1 = vb1; W2 = vW2; b2 = vb2; outg = g_v; }

    const int tok0 = blockIdx.x * TOK;

    __shared__ float xs[F_ * XSTR];      //  9216 B, layout [feature][token]
    __shared__ float hsm[HID_ * XSTR];   // 36864 B, layout [hidden ][token]

    // Load x tile transposed: [TOK][F] global -> [F][TOK] smem
    {
        const float4* xg = (const float4*)(x + tok0 * F_);
        #pragma unroll
        for (int r = 0; r < 2; r++) {
            const int g  = tid + r * 256;        // float4 index
            const int t  = g >> 4;               // token
            const int fb = (g & 15) * 4;         // feature base
            const float4 v = xg[g];
            xs[(fb + 0) * XSTR + t] = v.x;
            xs[(fb + 1) * XSTR + t] = v.y;
            xs[(fb + 2) * XSTR + t] = v.z;
            xs[(fb + 3) * XSTR + t] = v.w;
        }
    }
    __syncthreads();

    // ---- Phase 1: hidden = elu(x @ W1 + b1); thread = hidden channel
    {
        u64 acc[16];
        #pragma unroll
        for (int e = 0; e < 16; e++) acc[e] = 0ull;

        #pragma unroll 4
        for (int i = 0; i < F_; i++) {
            const float w = __ldg(&W1[i * HID_ + tid]);
            const u64 wb = pk2(w, w);
            const ulonglong2* xr = (const ulonglong2*)(xs + i * XSTR);
            #pragma unroll
            for (int u = 0; u < 8; u++) {
                const ulonglong2 xp = xr[u];
                acc[2 * u + 0] = fma2(wb, xp.x, acc[2 * u + 0]);
                acc[2 * u + 1] = fma2(wb, xp.y, acc[2 * u + 1]);
            }
        }
        const float bb = b1[tid];
        #pragma unroll
        for (int e = 0; e < 16; e++) {
            float a, b;
            upk2(acc[e], a, b);
            a += bb; b += bb;
            hsm[tid * XSTR + 2 * e + 0] = (a > 0.f) ? a : (__expf(a) - 1.f);
            hsm[tid * XSTR + 2 * e + 1] = (b > 0.f) ? b : (__expf(b) - 1.f);
        }
    }
    __syncthreads();

    // ---- Phase 2: out = hidden @ W2 + b2; thread = (out channel, token half)
    {
        const int j  = tid & 127;
        const int tg = tid >> 7;
        u64 acc[8];
        #pragma unroll
        for (int e = 0; e < 8; e++) acc[e] = 0ull;

        #pragma unroll 4
        for (int i = 0; i < HID_; i++) {
            const float w = __ldg(&W2[i * D_ + j]);
            const u64 wb = pk2(w, w);
            const ulonglong2* hr = (const ulonglong2*)(hsm + i * XSTR + tg * 16);
            #pragma unroll
            for (int u = 0; u < 4; u++) {
                const ulonglong2 hp = hr[u];
                acc[2 * u + 0] = fma2(wb, hp.x, acc[2 * u + 0]);
                acc[2 * u + 1] = fma2(wb, hp.y, acc[2 * u + 1]);
            }
        }
        const float bb = b2[j];
        const int h  = j >> 4;
        const int dk = j & 15;
        #pragma unroll
        for (int e = 0; e < 8; e++) {
            float a, b;
            upk2(acc[e], a, b);
            const int tokA = tok0 + tg * 16 + 2 * e;
            const int bA   = tokA >> 11;
            const int sA   = tokA & (S_ - 1);
            const long base = ((long)(bA * H_ + h) * S_);
            outg[(base + sA) * DK_ + dk]     = a + bb;
            outg[(base + sA + 1) * DK_ + dk] = b + bb; // tokA+1 same batch (tok0 mult of 32)
        }
    }
}

// ============================================================
// Flash attention, f32x2-packed: 2 queries/thread, keys in pairs.
// grid (S/QT, B*H), 128 threads.
// ============================================================
__global__ void __launch_bounds__(128) attn_kernel()
{
    const int tid = threadIdx.x;
    const int bh  = blockIdx.y;
    const int qi0 = blockIdx.x * QT + 2 * tid;

    __shared__ float ksm[(CH / 2) * KSTR];   //  9216 B: pair-interleaved keys
    __shared__ float vsm[CH * VSTR];         // 10240 B: natural per-key rows
    __shared__ float red[128 * 17];          //  8704 B

    // Load + pre-scale both queries; build broadcast pairs
    u64 qb0[DK_], qb1[DK_];
    {
        const float4* qp = (const float4*)(g_q + ((long)bh * S_ + qi0) * DK_);
        #pragma unroll
        for (int u = 0; u < 4; u++) {
            float4 a = qp[u];
            float4 b = qp[u + 4];
            qb0[4 * u + 0] = pk2(a.x * 0.25f, a.x * 0.25f);
            qb0[4 * u + 1] = pk2(a.y * 0.25f, a.y * 0.25f);
            qb0[4 * u + 2] = pk2(a.z * 0.25f, a.z * 0.25f);
            qb0[4 * u + 3] = pk2(a.w * 0.25f, a.w * 0.25f);
            qb1[4 * u + 0] = pk2(b.x * 0.25f, b.x * 0.25f);
            qb1[4 * u + 1] = pk2(b.y * 0.25f, b.y * 0.25f);
            qb1[4 * u + 2] = pk2(b.z * 0.25f, b.z * 0.25f);
            qb1[4 * u + 3] = pk2(b.w * 0.25f, b.w * 0.25f);
        }
    }

    float m0 = -1e30f, l0 = 0.f;
    float m1 = -1e30f, l1 = 0.f;
    u64 acc0[8], acc1[8];
    #pragma unroll
    for (int e = 0; e < 8; e++) { acc0[e] = 0ull; acc1[e] = 0ull; }

    const float4* kg = (const float4*)(g_k + (long)bh * S_ * DK_);
    const float4* vg = (const float4*)(g_v + (long)bh * S_ * DK_);

    for (int c = 0; c < S_; c += CH) {
        __syncthreads();
        {
            const int j   = tid;              // key within chunk
            const int p   = j >> 1;
            const int par = j & 1;
            float4 kv[4];
            #pragma unroll
            for (int u = 0; u < 4; u++) kv[u] = kg[(c + j) * 4 + u];
            #pragma unroll
            for (int u = 0; u < 4; u++) {
                ksm[p * KSTR + 2 * (4 * u + 0) + par] = kv[u].x;
                ksm[p * KSTR + 2 * (4 * u + 1) + par] = kv[u].y;
                ksm[p * KSTR + 2 * (4 * u + 2) + par] = kv[u].z;
                ksm[p * KSTR + 2 * (4 * u + 3) + par] = kv[u].w;
            }
            float4* vr = (float4*)(vsm + j * VSTR);
            #pragma unroll
            for (int u = 0; u < 4; u++) vr[u] = vg[(c + j) * 4 + u];
        }
        __syncthreads();

        #pragma unroll 2
        for (int p = 0; p < CH / 2; p++) {
            const ulonglong2* kr = (const ulonglong2*)(ksm + p * KSTR);
            // QK: packed over (even,odd) key of the pair, 2 chains per query
            u64 sA0 = 0ull, sA1 = 0ull, sB0 = 0ull, sB1 = 0ull;
            #pragma unroll
            for (int t = 0; t < 8; t++) {
                const ulonglong2 kk = kr[t];
                sA0 = fma2(qb0[2 * t + 0], kk.x, sA0);
                sA1 = fma2(qb0[2 * t + 1], kk.y, sA1);
                sB0 = fma2(qb1[2 * t + 0], kk.x, sB0);
                sB1 = fma2(qb1[2 * t + 1], kk.y, sB1);
            }
            float sAe, sAo, sBe, sBo;
            upk2(add2(sA0, sA1), sAe, sAo);
            upk2(add2(sB0, sB1), sBe, sBo);

            // online softmax, query 0
            {
                const float mx = fmaxf(sAe, sAo);
                if (mx > m0) {
                    const float alpha = __expf(m0 - mx);
                    m0 = mx; l0 *= alpha;
                    const u64 ab = pk2(alpha, alpha);
                    #pragma unroll
                    for (int e = 0; e < 8; e++) acc0[e] = mul2(acc0[e], ab);
                }
            }
            // online softmax, query 1
            {
                const float mx = fmaxf(sBe, sBo);
                if (mx > m1) {
                    const float alpha = __expf(m1 - mx);
                    m1 = mx; l1 *= alpha;
                    const u64 ab = pk2(alpha, alpha);
                    #pragma unroll
                    for (int e = 0; e < 8; e++) acc1[e] = mul2(acc1[e], ab);
                }
            }
            const float pAe = __expf(sAe - m0), pAo = __expf(sAo - m0);
            const float pBe = __expf(sBe - m1), pBo = __expf(sBo - m1);
            l0 += pAe + pAo;
            l1 += pBe + pBo;
            const u64 pAeb = pk2(pAe, pAe), pAob = pk2(pAo, pAo);
            const u64 pBeb = pk2(pBe, pBe), pBob = pk2(pBo, pBo);

            const ulonglong2* ve = (const ulonglong2*)(vsm + (2 * p + 0) * VSTR);
            const ulonglong2* vo = (const ulonglong2*)(vsm + (2 * p + 1) * VSTR);
            #pragma unroll
            for (int u = 0; u < 4; u++) {
                const ulonglong2 a = ve[u];
                const ulonglong2 b = vo[u];
                acc0[2 * u + 0] = fma2(pAeb, a.x, acc0[2 * u + 0]);
                acc0[2 * u + 1] = fma2(pAeb, a.y, acc0[2 * u + 1]);
                acc0[2 * u + 0] = fma2(pAob, b.x, acc0[2 * u + 0]);
                acc0[2 * u + 1] = fma2(pAob, b.y, acc0[2 * u + 1]);
                acc1[2 * u + 0] = fma2(pBeb, a.x, acc1[2 * u + 0]);
                acc1[2 * u + 1] = fma2(pBeb, a.y, acc1[2 * u + 1]);
                acc1[2 * u + 0] = fma2(pBob, b.x, acc1[2 * u + 0]);
                acc1[2 * u + 1] = fma2(pBob, b.y, acc1[2 * u + 1]);
            }
        }
    }

    // normalize both queries, take elementwise max, block-reduce
    {
        const float i0 = 1.f / l0;
        const float i1 = 1.f / l1;
        #pragma unroll
        for (int e = 0; e < 8; e++) {
            float a0, b0, a1, b1;
            upk2(acc0[e], a0, b0);
            upk2(acc1[e], a1, b1);
            red[tid * 17 + 2 * e + 0] = fmaxf(a0 * i0, a1 * i1);
            red[tid * 17 + 2 * e + 1] = fmaxf(b0 * i0, b1 * i1);
        }
    }
    __syncthreads();

    for (int off = 64; off > 0; off >>= 1) {
        if (tid < off) {
            #pragma unroll
            for (int d = 0; d < DK_; d++)
                red[tid * 17 + d] = fmaxf(red[tid * 17 + d], red[(tid + off) * 17 + d]);
        }
        __syncthreads();
    }

    if (tid < DK_) {
        const int b = bh >> 3, h = bh & 7;
        atomicMax(&g_max[b * D_ + h * DK_ + tid], fkey(red[tid]));
    }
}

__global__ void finalize_kernel(float* __restrict__ out) {
    out[threadIdx.x] = ikey(g_max[threadIdx.x]);
}

extern "C" void kernel_launch(void* const* d_in, const int* in_sizes, int n_in,
                              void* d_out, int out_size)
{
    const float* x   = (const float*)d_in[0];
    const float* qW1 = (const float*)d_in[1];
    const float* qb1 = (const float*)d_in[2];
    const float* qW2 = (const float*)d_in[3];
    const float* qb2 = (const float*)d_in[4];
    const float* kW1 = (const float*)d_in[5];
    const float* kb1 = (const float*)d_in[6];
    const float* kW2 = (const float*)d_in[7];
    const float* kb2 = (const float*)d_in[8];
    const float* vW1 = (const float*)d_in[9];
    const float* vb1 = (const float*)d_in[10];
    const float* vW2 = (const float*)d_in[11];
    const float* vb2 = (const float*)d_in[12];

    init_kernel<<<1, B_ * D_>>>();

    dim3 gmlp(B_ * S_ / TOK, 3);
    qkv_mlp_kernel<<<gmlp, 256>>>(x, qW1, qb1, qW2, qb2,
                                     kW1, kb1, kW2, kb2,
                                     vW1, vb1, vW2, vb2);

    dim3 gatt(S_ / QT, B_ * H_);
    attn_kernel<<<gatt, QT / 2>>>();

    finalize_kernel<<<1, B_ * D_>>>((float*)d_out);
}

// round 4
// speedup vs baseline: 2.2091x; 2.0916x over previous
#include <cuda_runtime.h>
#include <cuda_bf16.h>
#include <cstdint>

#define B_   4
#define S_   2048
#define F_   64
#define HID_ 256
#define D_   128
#define H_   8
#define DK_  16

#define TOK  32
#define XSTR 36

typedef unsigned long long u64;
typedef unsigned int u32;

// Scratch: q/k/v in head-major layout [B*H, S, DK]
__device__ float    g_q[B_ * H_ * S_ * DK_];
__device__ float    g_k[B_ * H_ * S_ * DK_];
__device__ float    g_v[B_ * H_ * S_ * DK_];
__device__ unsigned g_max[B_ * D_];

// ---- order-preserving float <-> uint keys for atomicMax ----
__device__ __forceinline__ unsigned fkey(float f) {
    unsigned u = __float_as_uint(f);
    return (u & 0x80000000u) ? ~u : (u | 0x80000000u);
}
__device__ __forceinline__ float ikey(unsigned k) {
    unsigned u = (k & 0x80000000u) ? (k & 0x7FFFFFFFu) : ~k;
    return __uint_as_float(u);
}

__global__ void init_kernel() { g_max[threadIdx.x] = 0u; }
__global__ void finalize_kernel(float* __restrict__ out) {
    out[threadIdx.x] = ikey(g_max[threadIdx.x]);
}

// ---- packed f32x2 helpers (MLP) ----
__device__ __forceinline__ u64 pk2(float lo, float hi) {
    u64 r;
    asm("mov.b64 %0, {%1, %2};" : "=l"(r) : "r"(__float_as_uint(lo)), "r"(__float_as_uint(hi)));
    return r;
}
__device__ __forceinline__ void upk2(u64 v, float& lo, float& hi) {
    unsigned a, b;
    asm("mov.b64 {%0, %1}, %2;" : "=r"(a), "=r"(b) : "l"(v));
    lo = __uint_as_float(a); hi = __uint_as_float(b);
}
__device__ __forceinline__ u64 fma2(u64 a, u64 b, u64 c) {
    u64 d;
    asm("fma.rn.f32x2 %0, %1, %2, %3;" : "=l"(d) : "l"(a), "l"(b), "l"(c));
    return d;
}

// ---- bf16 pack helpers ----
// returns packed bf16x2: low 16 bits = lo_val, high 16 bits = hi_val
__device__ __forceinline__ u32 pkbf(float lo_val, float hi_val) {
    u32 d;
    asm("cvt.rn.bf16x2.f32 %0, %1, %2;" : "=r"(d) : "f"(hi_val), "f"(lo_val));
    return d;
}
__device__ __forceinline__ float bflo(u32 p) { return __uint_as_float(p << 16); }
__device__ __forceinline__ float bfhi(u32 p) { return __uint_as_float(p & 0xFFFF0000u); }

// ---- bf16 mma m16n8k16 ----
__device__ __forceinline__ void mma_bf16(float d[4], const u32 a[4], u32 b0, u32 b1) {
    asm volatile(
        "mma.sync.aligned.m16n8k16.row.col.f32.bf16.bf16.f32 "
        "{%0,%1,%2,%3}, {%4,%5,%6,%7}, {%8,%9}, {%0,%1,%2,%3};"
        : "+f"(d[0]), "+f"(d[1]), "+f"(d[2]), "+f"(d[3])
        : "r"(a[0]), "r"(a[1]), "r"(a[2]), "r"(a[3]), "r"(b0), "r"(b1));
}

#define QSTR 40    // bf16 per Q/K smem row (32 data + 8 pad) -> 80B stride, bank-clean
#define VSTR 136   // bf16 per Vt row (128 data + 8 pad) -> 272B stride, bank-clean

// ============================================================
// bf16 mma.sync flash attention (no max subtraction; logits ~N(0,0.11)).
// grid (S/128, B*H), 256 threads = 8 warps x 16 query rows.
// ============================================================
__global__ void __launch_bounds__(256) attn_mma_kernel()
{
    __shared__ unsigned short Qs[128][QSTR];     // [q][0:16 hi | 16:32 lo]
    __shared__ unsigned short Ks[128][QSTR];     // [key][0:16 hi | 16:32 lo]
    __shared__ unsigned short Vthi[16][VSTR];    // [dk][key]
    __shared__ unsigned short Vtlo[16][VSTR];

    const int tid  = threadIdx.x;
    const int lane = tid & 31;
    const int warp = tid >> 5;
    const int gID  = lane >> 2;     // 0..7
    const int tig  = lane & 3;      // 0..3
    const int bh   = blockIdx.y;
    const int q0   = blockIdx.x * 128;

    // ---- load + split Q tile (scale 0.25 folded in) ----
    {
        const int r  = tid >> 1;
        const int d0 = (tid & 1) * 8;
        const float4* qp = (const float4*)(g_q + ((size_t)bh * S_ + q0 + r) * DK_ + d0);
        const float4 v0 = qp[0], v1 = qp[1];
        float f[8] = {v0.x, v0.y, v0.z, v0.w, v1.x, v1.y, v1.z, v1.w};
        #pragma unroll
        for (int j = 0; j < 4; j++) {
            const float x0 = f[2 * j] * 0.25f, x1 = f[2 * j + 1] * 0.25f;
            const u32 hp = pkbf(x0, x1);
            const u32 lp = pkbf(x0 - bflo(hp), x1 - bfhi(hp));
            *(u32*)&Qs[r][d0 + 2 * j]      = hp;
            *(u32*)&Qs[r][16 + d0 + 2 * j] = lp;
        }
    }
    __syncthreads();

    // ---- Q A-fragments for this warp (rows warp*16 + gID, +8) ----
    u32 qa_hi[4], qa_lo[4];
    {
        const int ra = warp * 16 + gID;
        qa_hi[0] = *(const u32*)&Qs[ra][2 * tig];
        qa_hi[1] = *(const u32*)&Qs[ra + 8][2 * tig];
        qa_hi[2] = *(const u32*)&Qs[ra][2 * tig + 8];
        qa_hi[3] = *(const u32*)&Qs[ra + 8][2 * tig + 8];
        qa_lo[0] = *(const u32*)&Qs[ra][16 + 2 * tig];
        qa_lo[1] = *(const u32*)&Qs[ra + 8][16 + 2 * tig];
        qa_lo[2] = *(const u32*)&Qs[ra][16 + 2 * tig + 8];
        qa_lo[3] = *(const u32*)&Qs[ra + 8][16 + 2 * tig + 8];
    }

    float out0[4] = {0.f, 0.f, 0.f, 0.f};   // dk 0-7
    float out1[4] = {0.f, 0.f, 0.f, 0.f};   // dk 8-15
    float ls0 = 0.f, ls1 = 0.f;             // row sums (rows ra, ra+8), partial over cols

    for (int t = 0; t < S_ / 128; t++) {
        __syncthreads();
        // ---- fill K tile (key-major, hi|lo) ----
        {
            const int r  = tid >> 1;
            const int d0 = (tid & 1) * 8;
            const size_t base = ((size_t)bh * S_ + t * 128 + r) * DK_ + d0;
            const float4* kp = (const float4*)(g_k + base);
            const float4 v0 = kp[0], v1 = kp[1];
            float f[8] = {v0.x, v0.y, v0.z, v0.w, v1.x, v1.y, v1.z, v1.w};
            #pragma unroll
            for (int j = 0; j < 4; j++) {
                const u32 hp = pkbf(f[2 * j], f[2 * j + 1]);
                const u32 lp = pkbf(f[2 * j] - bflo(hp), f[2 * j + 1] - bfhi(hp));
                *(u32*)&Ks[r][d0 + 2 * j]      = hp;
                *(u32*)&Ks[r][16 + d0 + 2 * j] = lp;
            }
            // ---- fill V transposed (dk-major, hi/lo separate) ----
            const float4* vp = (const float4*)(g_v + base);
            const float4 w0 = vp[0], w1 = vp[1];
            float g[8] = {w0.x, w0.y, w0.z, w0.w, w1.x, w1.y, w1.z, w1.w};
            #pragma unroll
            for (int j = 0; j < 8; j++) {
                const __nv_bfloat16 h = __float2bfloat16(g[j]);
                const float res = g[j] - __bfloat162float(h);
                Vthi[d0 + j][r] = __bfloat16_as_ushort(h);
                Vtlo[d0 + j][r] = __bfloat16_as_ushort(__float2bfloat16(res));
            }
        }
        __syncthreads();

        #pragma unroll
        for (int half = 0; half < 2; half++) {
            u32 pa_hi[8], pb_hi[8], pa_lo[8], pb_lo[8];

            // ---- QK scores for 8 n-tiles (64 keys), exp, pack ----
            #pragma unroll
            for (int j = 0; j < 8; j++) {
                const int kb = half * 64 + j * 8;       // key base of n-tile
                const int kn = kb + gID;                // this thread's key col
                const u32 bh0 = *(const u32*)&Ks[kn][2 * tig];
                const u32 bh1 = *(const u32*)&Ks[kn][2 * tig + 8];
                const u32 bl0 = *(const u32*)&Ks[kn][16 + 2 * tig];
                const u32 bl1 = *(const u32*)&Ks[kn][16 + 2 * tig + 8];
                float d[4] = {0.f, 0.f, 0.f, 0.f};
                mma_bf16(d, qa_hi, bh0, bh1);
                mma_bf16(d, qa_lo, bh0, bh1);
                mma_bf16(d, qa_hi, bl0, bl1);

                const float p0 = __expf(d[0]);
                const float p1 = __expf(d[1]);
                const float p2 = __expf(d[2]);
                const float p3 = __expf(d[3]);
                ls0 += p0 + p1;
                ls1 += p2 + p3;

                const u32 ha = pkbf(p0, p1);
                const u32 hb = pkbf(p2, p3);
                pa_hi[j] = ha;
                pb_hi[j] = hb;
                pa_lo[j] = pkbf(p0 - bflo(ha), p1 - bfhi(ha));
                pb_lo[j] = pkbf(p2 - bflo(hb), p3 - bfhi(hb));
            }

            // ---- PV: 4 k-steps of 16 keys ----
            #pragma unroll
            for (int ks = 0; ks < 4; ks++) {
                const u32 A_hi[4] = {pa_hi[2 * ks], pb_hi[2 * ks], pa_hi[2 * ks + 1], pb_hi[2 * ks + 1]};
                const u32 A_lo[4] = {pa_lo[2 * ks], pb_lo[2 * ks], pa_lo[2 * ks + 1], pb_lo[2 * ks + 1]};
                const int kb2 = half * 64 + ks * 16 + 2 * tig;
                {
                    const int dr = gID;
                    const u32 vh0 = *(const u32*)&Vthi[dr][kb2];
                    const u32 vh1 = *(const u32*)&Vthi[dr][kb2 + 8];
                    const u32 vl0 = *(const u32*)&Vtlo[dr][kb2];
                    const u32 vl1 = *(const u32*)&Vtlo[dr][kb2 + 8];
                    mma_bf16(out0, A_hi, vh0, vh1);
                    mma_bf16(out0, A_lo, vh0, vh1);
                    mma_bf16(out0, A_hi, vl0, vl1);
                }
                {
                    const int dr = 8 + gID;
                    const u32 vh0 = *(const u32*)&Vthi[dr][kb2];
                    const u32 vh1 = *(const u32*)&Vthi[dr][kb2 + 8];
                    const u32 vl0 = *(const u32*)&Vtlo[dr][kb2];
                    const u32 vl1 = *(const u32*)&Vtlo[dr][kb2 + 8];
                    mma_bf16(out1, A_hi, vh0, vh1);
                    mma_bf16(out1, A_lo, vh0, vh1);
                    mma_bf16(out1, A_hi, vl0, vl1);
                }
            }
        }
    }

    // ---- complete row sums across the quad (cols tig) ----
    ls0 += __shfl_xor_sync(0xFFFFFFFFu, ls0, 1);
    ls0 += __shfl_xor_sync(0xFFFFFFFFu, ls0, 2);
    ls1 += __shfl_xor_sync(0xFFFFFFFFu, ls1, 1);
    ls1 += __shfl_xor_sync(0xFFFFFFFFu, ls1, 2);
    const float i0 = 1.f / ls0;
    const float i1 = 1.f / ls1;

    // ---- write normalized outputs to smem [128 rows][17] (reuse Ks) ----
    __syncthreads();
    float* red = (float*)&Ks[0][0];
    {
        const int ra = warp * 16 + gID;
        const int c0 = 2 * tig;
        red[ra * 17 + c0 + 0]       = out0[0] * i0;
        red[ra * 17 + c0 + 1]       = out0[1] * i0;
        red[(ra + 8) * 17 + c0 + 0] = out0[2] * i1;
        red[(ra + 8) * 17 + c0 + 1] = out0[3] * i1;
        red[ra * 17 + 8 + c0 + 0]       = out1[0] * i0;
        red[ra * 17 + 8 + c0 + 1]       = out1[1] * i0;
        red[(ra + 8) * 17 + 8 + c0 + 0] = out1[2] * i1;
        red[(ra + 8) * 17 + 8 + c0 + 1] = out1[3] * i1;
    }
    __syncthreads();

    // ---- column max over 128 rows ----
    float* part = (float*)&Qs[0][0];   // [16][16]
    {
        const int c  = tid & 15;
        const int r0 = tid >> 4;       // 0..15
        float m = red[r0 * 17 + c];
        #pragma unroll
        for (int i = 1; i < 8; i++)
            m = fmaxf(m, red[(r0 + 16 * i) * 17 + c]);
        part[r0 * 16 + c] = m;
    }
    __syncthreads();
    if (tid < 16) {
        float m = part[tid];
        #pragma unroll
        for (int r = 1; r < 16; r++)
            m = fmaxf(m, part[r * 16 + tid]);
        const int b = bh >> 3, h = bh & 7;
        atomicMax(&g_max[b * D_ + h * DK_ + tid], fkey(m));
    }
}

// ============================================================
// Fused 2-layer MLP (f32x2), unchanged from R2.
// ============================================================
__global__ void __launch_bounds__(256) qkv_mlp_kernel(
    const float* __restrict__ x,
    const float* __restrict__ qW1, const float* __restrict__ qb1,
    const float* __restrict__ qW2, const float* __restrict__ qb2,
    const float* __restrict__ kW1, const float* __restrict__ kb1,
    const float* __restrict__ kW2, const float* __restrict__ kb2,
    const float* __restrict__ vW1, const float* __restrict__ vb1,
    const float* __restrict__ vW2, const float* __restrict__ vb2)
{
    const int tid = threadIdx.x;
    const int mlp = blockIdx.y;

    const float *W1, *b1, *W2, *b2;
    float* outg;
    if (mlp == 0)      { W1 = qW1; b1 = qb1; W2 = qW2; b2 = qb2; outg = g_q; }
    else if (mlp == 1) { W1 = kW1; b1 = kb1; W2 = kW2; b2 = kb2; outg = g_k; }
    else               { W1 = vW1; b1 = vb1; W2 = vW2; b2 = vb2; outg = g_v; }

    const int tok0 = blockIdx.x * TOK;

    __shared__ float xs[F_ * XSTR];
    __shared__ float hsm[HID_ * XSTR];

    {
        const float4* xg = (const float4*)(x + tok0 * F_);
        #pragma unroll
        for (int r = 0; r < 2; r++) {
            const int g  = tid + r * 256;
            const int t  = g >> 4;
            const int fb = (g & 15) * 4;
            const float4 v = xg[g];
            xs[(fb + 0) * XSTR + t] = v.x;
            xs[(fb + 1) * XSTR + t] = v.y;
            xs[(fb + 2) * XSTR + t] = v.z;
            xs[(fb + 3) * XSTR + t] = v.w;
        }
    }
    __syncthreads();

    {
        u64 acc[16];
        #pragma unroll
        for (int e = 0; e < 16; e++) acc[e] = 0ull;

        #pragma unroll 4
        for (int i = 0; i < F_; i++) {
            const float w = __ldg(&W1[i * HID_ + tid]);
            const u64 wb = pk2(w, w);
            const ulonglong2* xr = (const ulonglong2*)(xs + i * XSTR);
            #pragma unroll
            for (int u = 0; u < 8; u++) {
                const ulonglong2 xp = xr[u];
                acc[2 * u + 0] = fma2(wb, xp.x, acc[2 * u + 0]);
                acc[2 * u + 1] = fma2(wb, xp.y, acc[2 * u + 1]);
            }
        }
        const float bb = b1[tid];
        #pragma unroll
        for (int e = 0; e < 16; e++) {
            float a, b;
            upk2(acc[e], a, b);
            a += bb; b += bb;
            hsm[tid * XSTR + 2 * e + 0] = (a > 0.f) ? a : (__expf(a) - 1.f);
            hsm[tid * XSTR + 2 * e + 1] = (b > 0.f) ? b : (__expf(b) - 1.f);
        }
    }
    __syncthreads();

    {
        const int j  = tid & 127;
        const int tg = tid >> 7;
        u64 acc[8];
        #pragma unroll
        for (int e = 0; e < 8; e++) acc[e] = 0ull;

        #pragma unroll 4
        for (int i = 0; i < HID_; i++) {
            const float w = __ldg(&W2[i * D_ + j]);
            const u64 wb = pk2(w, w);
            const ulonglong2* hr = (const ulonglong2*)(hsm + i * XSTR + tg * 16);
            #pragma unroll
            for (int u = 0; u < 4; u++) {
                const ulonglong2 hp = hr[u];
                acc[2 * u + 0] = fma2(wb, hp.x, acc[2 * u + 0]);
                acc[2 * u + 1] = fma2(wb, hp.y, acc[2 * u + 1]);
            }
        }
        const float bb = b2[j];
        const int h   = j >> 4;
        const int dkc = j & 15;
        #pragma unroll
        for (int e = 0; e < 8; e++) {
            float a, b;
            upk2(acc[e], a, b);
            const int tokA = tok0 + tg * 16 + 2 * e;
            const int bA   = tokA >> 11;
            const int sA   = tokA & (S_ - 1);
            const long base = ((long)(bA * H_ + h) * S_);
            outg[(base + sA) * DK_ + dkc]     = a + bb;
            outg[(base + sA + 1) * DK_ + dkc] = b + bb;
        }
    }
}

extern "C" void kernel_launch(void* const* d_in, const int* in_sizes, int n_in,
                              void* d_out, int out_size)
{
    const float* x   = (const float*)d_in[0];
    const float* qW1 = (const float*)d_in[1];
    const float* qb1 = (const float*)d_in[2];
    const float* qW2 = (const float*)d_in[3];
    const float* qb2 = (const float*)d_in[4];
    const float* kW1 = (const float*)d_in[5];
    const float* kb1 = (const float*)d_in[6];
    const float* kW2 = (const float*)d_in[7];
    const float* kb2 = (const float*)d_in[8];
    const float* vW1 = (const float*)d_in[9];
    const float* vb1 = (const float*)d_in[10];
    const float* vW2 = (const float*)d_in[11];
    const float* vb2 = (const float*)d_in[12];

    init_kernel<<<1, B_ * D_>>>();

    dim3 gmlp(B_ * S_ / TOK, 3);
    qkv_mlp_kernel<<<gmlp, 256>>>(x, qW1, qb1, qW2, qb2,
                                     kW1, kb1, kW2, kb2,
                                     vW1, vb1, vW2, vb2);

    dim3 gatt(S_ / 128, B_ * H_);
    attn_mma_kernel<<<gatt, 256>>>();

    finalize_kernel<<<1, B_ * D_>>>((float*)d_out);
}

// round 5
// speedup vs baseline: 2.2549x; 1.0207x over previous
#include <cuda_runtime.h>
#include <cuda_bf16.h>
#include <cstdint>

#define B_   4
#define S_   2048
#define F_   64
#define HID_ 256
#define D_   128
#define H_   8
#define DK_  16

#define TOK  32
#define XSTR 36

typedef unsigned long long u64;
typedef unsigned int u32;
typedef unsigned short u16;

// Pre-split bf16 operands, produced by the MLP epilogue:
//  g_qs/g_ks: [bh][s][0:16 hi | 16:32 lo]  (Q pre-scaled by 0.25)
//  g_vthi/g_vtlo: [bh][dk][s]  (V transposed)
__device__ __align__(16) u16 g_qs[B_ * H_ * S_ * 32];
__device__ __align__(16) u16 g_ks[B_ * H_ * S_ * 32];
__device__ __align__(16) u16 g_vthi[B_ * H_ * 16 * S_];
__device__ __align__(16) u16 g_vtlo[B_ * H_ * 16 * S_];
__device__ unsigned g_max[B_ * D_];

// ---- order-preserving float <-> uint keys for atomicMax ----
__device__ __forceinline__ unsigned fkey(float f) {
    unsigned u = __float_as_uint(f);
    return (u & 0x80000000u) ? ~u : (u | 0x80000000u);
}
__device__ __forceinline__ float ikey(unsigned k) {
    unsigned u = (k & 0x80000000u) ? (k & 0x7FFFFFFFu) : ~k;
    return __uint_as_float(u);
}

__global__ void init_kernel() { g_max[threadIdx.x] = 0u; }
__global__ void finalize_kernel(float* __restrict__ out) {
    out[threadIdx.x] = ikey(g_max[threadIdx.x]);
}

// ---- packed f32x2 helpers (MLP) ----
__device__ __forceinline__ u64 pk2(float lo, float hi) {
    u64 r;
    asm("mov.b64 %0, {%1, %2};" : "=l"(r) : "r"(__float_as_uint(lo)), "r"(__float_as_uint(hi)));
    return r;
}
__device__ __forceinline__ void upk2(u64 v, float& lo, float& hi) {
    unsigned a, b;
    asm("mov.b64 {%0, %1}, %2;" : "=r"(a), "=r"(b) : "l"(v));
    lo = __uint_as_float(a); hi = __uint_as_float(b);
}
__device__ __forceinline__ u64 fma2(u64 a, u64 b, u64 c) {
    u64 d;
    asm("fma.rn.f32x2 %0, %1, %2, %3;" : "=l"(d) : "l"(a), "l"(b), "l"(c));
    return d;
}

// ---- bf16 pack helpers ----
__device__ __forceinline__ u32 pkbf(float lo_val, float hi_val) {
    u32 d;
    asm("cvt.rn.bf16x2.f32 %0, %1, %2;" : "=r"(d) : "f"(hi_val), "f"(lo_val));
    return d;
}
__device__ __forceinline__ float bflo(u32 p) { return __uint_as_float(p << 16); }
__device__ __forceinline__ float bfhi(u32 p) { return __uint_as_float(p & 0xFFFF0000u); }

__device__ __forceinline__ void split_bf(float v, u16& hi, u16& lo) {
    const __nv_bfloat16 h = __float2bfloat16(v);
    hi = __bfloat16_as_ushort(h);
    lo = __bfloat16_as_ushort(__float2bfloat16(v - __bfloat162float(h)));
}

// ---- bf16 mma m16n8k16 ----
__device__ __forceinline__ void mma_bf16(float d[4], const u32 a[4], u32 b0, u32 b1) {
    asm volatile(
        "mma.sync.aligned.m16n8k16.row.col.f32.bf16.bf16.f32 "
        "{%0,%1,%2,%3}, {%4,%5,%6,%7}, {%8,%9}, {%0,%1,%2,%3};"
        : "+f"(d[0]), "+f"(d[1]), "+f"(d[2]), "+f"(d[3])
        : "r"(a[0]), "r"(a[1]), "r"(a[2]), "r"(a[3]), "r"(b0), "r"(b1));
}

#define QSTR 40    // u16 per Q/K smem row (32 data + 8 pad) -> 80B stride (16B-aligned)
#define VSTR 136   // u16 per Vt row (128 data + 8 pad) -> 272B stride (16B-aligned)

// ============================================================
// bf16 mma.sync flash attention (no max subtraction; logits small).
// grid (S/128, B*H), 256 threads = 8 warps x 16 query rows.
// ============================================================
__global__ void __launch_bounds__(256) attn_mma_kernel()
{
    __shared__ u16 Qs[128][QSTR];
    __shared__ u16 Ks[128][QSTR];
    __shared__ u16 Vthi[16][VSTR];
    __shared__ u16 Vtlo[16][VSTR];

    const int tid  = threadIdx.x;
    const int lane = tid & 31;
    const int warp = tid >> 5;
    const int gID  = lane >> 2;
    const int tig  = lane & 3;
    const int bh   = blockIdx.y;
    const int q0   = blockIdx.x * 128;

    // ---- Q tile: pure 16B copies (pre-split, pre-scaled) ----
    #pragma unroll
    for (int cc = 0; cc < 2; cc++) {
        const int c    = tid + cc * 256;
        const int r    = c >> 2;
        const int part = c & 3;
        const uint4 v = *(const uint4*)&g_qs[((size_t)bh * S_ + q0 + r) * 32 + part * 8];
        *(uint4*)&Qs[r][part * 8] = v;
    }
    __syncthreads();

    // ---- Q A-fragments ----
    u32 qa_hi[4], qa_lo[4];
    {
        const int ra = warp * 16 + gID;
        qa_hi[0] = *(const u32*)&Qs[ra][2 * tig];
        qa_hi[1] = *(const u32*)&Qs[ra + 8][2 * tig];
        qa_hi[2] = *(const u32*)&Qs[ra][2 * tig + 8];
        qa_hi[3] = *(const u32*)&Qs[ra + 8][2 * tig + 8];
        qa_lo[0] = *(const u32*)&Qs[ra][16 + 2 * tig];
        qa_lo[1] = *(const u32*)&Qs[ra + 8][16 + 2 * tig];
        qa_lo[2] = *(const u32*)&Qs[ra][16 + 2 * tig + 8];
        qa_lo[3] = *(const u32*)&Qs[ra + 8][16 + 2 * tig + 8];
    }

    float out0[4] = {0.f, 0.f, 0.f, 0.f};
    float out1[4] = {0.f, 0.f, 0.f, 0.f};
    float ls0 = 0.f, ls1 = 0.f;

    for (int t = 0; t < S_ / 128; t++) {
        __syncthreads();
        // ---- K tile: 16B copies ----
        #pragma unroll
        for (int cc = 0; cc < 2; cc++) {
            const int c    = tid + cc * 256;
            const int r    = c >> 2;
            const int part = c & 3;
            const uint4 v = *(const uint4*)&g_ks[((size_t)bh * S_ + t * 128 + r) * 32 + part * 8];
            *(uint4*)&Ks[r][part * 8] = v;
        }
        // ---- V tile: 16B copies (already transposed) ----
        {
            const int dk  = tid >> 4;
            const int off = tid & 15;
            const size_t gi = ((size_t)bh * 16 + dk) * S_ + t * 128 + off * 8;
            *(uint4*)&Vthi[dk][off * 8] = *(const uint4*)&g_vthi[gi];
            *(uint4*)&Vtlo[dk][off * 8] = *(const uint4*)&g_vtlo[gi];
        }
        __syncthreads();

        #pragma unroll
        for (int half = 0; half < 2; half++) {
            u32 pa_hi[8], pb_hi[8], pa_lo[8], pb_lo[8];

            #pragma unroll
            for (int j = 0; j < 8; j++) {
                const int kn = half * 64 + j * 8 + gID;
                const u32 bh0 = *(const u32*)&Ks[kn][2 * tig];
                const u32 bh1 = *(const u32*)&Ks[kn][2 * tig + 8];
                const u32 bl0 = *(const u32*)&Ks[kn][16 + 2 * tig];
                const u32 bl1 = *(const u32*)&Ks[kn][16 + 2 * tig + 8];
                float d[4] = {0.f, 0.f, 0.f, 0.f};
                mma_bf16(d, qa_hi, bh0, bh1);
                mma_bf16(d, qa_lo, bh0, bh1);
                mma_bf16(d, qa_hi, bl0, bl1);

                const float p0 = __expf(d[0]);
                const float p1 = __expf(d[1]);
                const float p2 = __expf(d[2]);
                const float p3 = __expf(d[3]);
                ls0 += p0 + p1;
                ls1 += p2 + p3;

                const u32 ha = pkbf(p0, p1);
                const u32 hb = pkbf(p2, p3);
                pa_hi[j] = ha;
                pb_hi[j] = hb;
                pa_lo[j] = pkbf(p0 - bflo(ha), p1 - bfhi(ha));
                pb_lo[j] = pkbf(p2 - bflo(hb), p3 - bfhi(hb));
            }

            #pragma unroll
            for (int ks = 0; ks < 4; ks++) {
                const u32 A_hi[4] = {pa_hi[2 * ks], pb_hi[2 * ks], pa_hi[2 * ks + 1], pb_hi[2 * ks + 1]};
                const u32 A_lo[4] = {pa_lo[2 * ks], pb_lo[2 * ks], pa_lo[2 * ks + 1], pb_lo[2 * ks + 1]};
                const int kb2 = half * 64 + ks * 16 + 2 * tig;
                {
                    const int dr = gID;
                    const u32 vh0 = *(const u32*)&Vthi[dr][kb2];
                    const u32 vh1 = *(const u32*)&Vthi[dr][kb2 + 8];
                    const u32 vl0 = *(const u32*)&Vtlo[dr][kb2];
                    const u32 vl1 = *(const u32*)&Vtlo[dr][kb2 + 8];
                    mma_bf16(out0, A_hi, vh0, vh1);
                    mma_bf16(out0, A_lo, vh0, vh1);
                    mma_bf16(out0, A_hi, vl0, vl1);
                }
                {
                    const int dr = 8 + gID;
                    const u32 vh0 = *(const u32*)&Vthi[dr][kb2];
                    const u32 vh1 = *(const u32*)&Vthi[dr][kb2 + 8];
                    const u32 vl0 = *(const u32*)&Vtlo[dr][kb2];
                    const u32 vl1 = *(const u32*)&Vtlo[dr][kb2 + 8];
                    mma_bf16(out1, A_hi, vh0, vh1);
                    mma_bf16(out1, A_lo, vh0, vh1);
                    mma_bf16(out1, A_hi, vl0, vl1);
                }
            }
        }
    }

    // ---- row sums across quad ----
    ls0 += __shfl_xor_sync(0xFFFFFFFFu, ls0, 1);
    ls0 += __shfl_xor_sync(0xFFFFFFFFu, ls0, 2);
    ls1 += __shfl_xor_sync(0xFFFFFFFFu, ls1, 1);
    ls1 += __shfl_xor_sync(0xFFFFFFFFu, ls1, 2);
    const float i0 = 1.f / ls0;
    const float i1 = 1.f / ls1;

    __syncthreads();
    float* red = (float*)&Ks[0][0];
    {
        const int ra = warp * 16 + gID;
        const int c0 = 2 * tig;
        red[ra * 17 + c0 + 0]       = out0[0] * i0;
        red[ra * 17 + c0 + 1]       = out0[1] * i0;
        red[(ra + 8) * 17 + c0 + 0] = out0[2] * i1;
        red[(ra + 8) * 17 + c0 + 1] = out0[3] * i1;
        red[ra * 17 + 8 + c0 + 0]       = out1[0] * i0;
        red[ra * 17 + 8 + c0 + 1]       = out1[1] * i0;
        red[(ra + 8) * 17 + 8 + c0 + 0] = out1[2] * i1;
        red[(ra + 8) * 17 + 8 + c0 + 1] = out1[3] * i1;
    }
    __syncthreads();

    float* part = (float*)&Qs[0][0];
    {
        const int c  = tid & 15;
        const int r0 = tid >> 4;
        float m = red[r0 * 17 + c];
        #pragma unroll
        for (int i = 1; i < 8; i++)
            m = fmaxf(m, red[(r0 + 16 * i) * 17 + c]);
        part[r0 * 16 + c] = m;
    }
    __syncthreads();
    if (tid < 16) {
        float m = part[tid];
        #pragma unroll
        for (int r = 1; r < 16; r++)
            m = fmaxf(m, part[r * 16 + tid]);
        const int b = bh >> 3, h = bh & 7;
        atomicMax(&g_max[b * D_ + h * DK_ + tid], fkey(m));
    }
}

// ============================================================
// Fused 2-layer MLP (f32x2); epilogue writes pre-split bf16.
// ============================================================
__global__ void __launch_bounds__(256) qkv_mlp_kernel(
    const float* __restrict__ x,
    const float* __restrict__ qW1, const float* __restrict__ qb1,
    const float* __restrict__ qW2, const float* __restrict__ qb2,
    const float* __restrict__ kW1, const float* __restrict__ kb1,
    const float* __restrict__ kW2, const float* __restrict__ kb2,
    const float* __restrict__ vW1, const float* __restrict__ vb1,
    const float* __restrict__ vW2, const float* __restrict__ vb2)
{
    const int tid = threadIdx.x;
    const int mlp = blockIdx.y;

    const float *W1, *b1, *W2, *b2;
    if (mlp == 0)      { W1 = qW1; b1 = qb1; W2 = qW2; b2 = qb2; }
    else if (mlp == 1) { W1 = kW1; b1 = kb1; W2 = kW2; b2 = kb2; }
    else               { W1 = vW1; b1 = vb1; W2 = vW2; b2 = vb2; }

    const int tok0 = blockIdx.x * TOK;

    __shared__ float xs[F_ * XSTR];
    __shared__ float hsm[HID_ * XSTR];

    {
        const float4* xg = (const float4*)(x + tok0 * F_);
        #pragma unroll
        for (int r = 0; r < 2; r++) {
            const int g  = tid + r * 256;
            const int t  = g >> 4;
            const int fb = (g & 15) * 4;
            const float4 v = xg[g];
            xs[(fb + 0) * XSTR + t] = v.x;
            xs[(fb + 1) * XSTR + t] = v.y;
            xs[(fb + 2) * XSTR + t] = v.z;
            xs[(fb + 3) * XSTR + t] = v.w;
        }
    }
    __syncthreads();

    {
        u64 acc[16];
        #pragma unroll
        for (int e = 0; e < 16; e++) acc[e] = 0ull;

        #pragma unroll 4
        for (int i = 0; i < F_; i++) {
            const float w = __ldg(&W1[i * HID_ + tid]);
            const u64 wb = pk2(w, w);
            const ulonglong2* xr = (const ulonglong2*)(xs + i * XSTR);
            #pragma unroll
            for (int u = 0; u < 8; u++) {
                const ulonglong2 xp = xr[u];
                acc[2 * u + 0] = fma2(wb, xp.x, acc[2 * u + 0]);
                acc[2 * u + 1] = fma2(wb, xp.y, acc[2 * u + 1]);
            }
        }
        const float bb = b1[tid];
        #pragma unroll
        for (int e = 0; e < 16; e++) {
            float a, b;
            upk2(acc[e], a, b);
            a += bb; b += bb;
            hsm[tid * XSTR + 2 * e + 0] = (a > 0.f) ? a : (__expf(a) - 1.f);
            hsm[tid * XSTR + 2 * e + 1] = (b > 0.f) ? b : (__expf(b) - 1.f);
        }
    }
    __syncthreads();

    {
        const int j  = tid & 127;
        const int tg = tid >> 7;
        u64 acc[8];
        #pragma unroll
        for (int e = 0; e < 8; e++) acc[e] = 0ull;

        #pragma unroll 4
        for (int i = 0; i < HID_; i++) {
            const float w = __ldg(&W2[i * D_ + j]);
            const u64 wb = pk2(w, w);
            const ulonglong2* hr = (const ulonglong2*)(hsm + i * XSTR + tg * 16);
            #pragma unroll
            for (int u = 0; u < 4; u++) {
                const ulonglong2 hp = hr[u];
                acc[2 * u + 0] = fma2(wb, hp.x, acc[2 * u + 0]);
                acc[2 * u + 1] = fma2(wb, hp.y, acc[2 * u + 1]);
            }
        }
        const float bb = b2[j];
        const int h   = j >> 4;
        const int dkc = j & 15;
        #pragma unroll
        for (int e = 0; e < 8; e++) {
            float a, b;
            upk2(acc[e], a, b);
            float va = a + bb, vb = b + bb;
            if (mlp == 0) { va *= 0.25f; vb *= 0.25f; }
            u16 hA, lA, hB, lB;
            split_bf(va, hA, lA);
            split_bf(vb, hB, lB);

            const int tokA = tok0 + tg * 16 + 2 * e;
            const int bA   = tokA >> 11;
            const int sA   = tokA & (S_ - 1);
            const int bhD  = bA * H_ + h;
            if (mlp < 2) {
                u16* base = (mlp == 0) ? g_qs : g_ks;
                const size_t r0 = ((size_t)bhD * S_ + sA) * 32;
                base[r0 + dkc]      = hA;
                base[r0 + 16 + dkc] = lA;
                base[r0 + 32 + dkc]      = hB;   // token sA+1
                base[r0 + 48 + dkc]      = lB;
            } else {
                const size_t vi = ((size_t)bhD * 16 + dkc) * S_ + sA;
                g_vthi[vi]     = hA;
                g_vthi[vi + 1] = hB;
                g_vtlo[vi]     = lA;
                g_vtlo[vi + 1] = lB;
            }
        }
    }
}

extern "C" void kernel_launch(void* const* d_in, const int* in_sizes, int n_in,
                              void* d_out, int out_size)
{
    const float* x   = (const float*)d_in[0];
    const float* qW1 = (const float*)d_in[1];
    const float* qb1 = (const float*)d_in[2];
    const float* qW2 = (const float*)d_in[3];
    const float* qb2 = (const float*)d_in[4];
    const float* kW1 = (const float*)d_in[5];
    const float* kb1 = (const float*)d_in[6];
    const float* kW2 = (const float*)d_in[7];
    const float* kb2 = (const float*)d_in[8];
    const float* vW1 = (const float*)d_in[9];
    const float* vb1 = (const float*)d_in[10];
    const float* vW2 = (const float*)d_in[11];
    const float* vb2 = (const float*)d_in[12];

    init_kernel<<<1, B_ * D_>>>();

    dim3 gmlp(B_ * S_ / TOK, 3);
    qkv_mlp_kernel<<<gmlp, 256>>>(x, qW1, qb1, qW2, qb2,
                                     kW1, kb1, kW2, kb2,
                                     vW1, vb1, vW2, vb2);

    dim3 gatt(S_ / 128, B_ * H_);
    attn_mma_kernel<<<gatt, 256>>>();

    finalize_kernel<<<1, B_ * D_>>>((float*)d_out);
}

// round 6
// speedup vs baseline: 2.9923x; 1.3271x over previous
#include <cuda_runtime.h>
#include <cuda_bf16.h>
#include <cuda_fp16.h>
#include <cstdint>

#define B_   4
#define S_   2048
#define F_   64
#define HID_ 256
#define D_   128
#define H_   8
#define DK_  16

#define TOK  32
#define XSTR 36

typedef unsigned long long u64;
typedef unsigned int u32;
typedef unsigned short u16;

// fp16 operands, produced by the MLP epilogue:
//  g_qs/g_ks: [bh][s][16]  (Q pre-scaled by 0.25)
//  g_vt:      [bh][dk][s]  (V transposed)
__device__ __align__(16) u16 g_qs[B_ * H_ * S_ * 16];
__device__ __align__(16) u16 g_ks[B_ * H_ * S_ * 16];
__device__ __align__(16) u16 g_vt[B_ * H_ * 16 * S_];
__device__ unsigned g_max[B_ * D_];

// ---- order-preserving float <-> uint keys for atomicMax ----
__device__ __forceinline__ unsigned fkey(float f) {
    unsigned u = __float_as_uint(f);
    return (u & 0x80000000u) ? ~u : (u | 0x80000000u);
}
__device__ __forceinline__ float ikey(unsigned k) {
    unsigned u = (k & 0x80000000u) ? (k & 0x7FFFFFFFu) : ~k;
    return __uint_as_float(u);
}

__global__ void init_kernel() { g_max[threadIdx.x] = 0u; }
__global__ void finalize_kernel(float* __restrict__ out) {
    out[threadIdx.x] = ikey(g_max[threadIdx.x]);
}

// ---- packed f32x2 helpers (MLP) ----
__device__ __forceinline__ u64 pk2(float lo, float hi) {
    u64 r;
    asm("mov.b64 %0, {%1, %2};" : "=l"(r) : "r"(__float_as_uint(lo)), "r"(__float_as_uint(hi)));
    return r;
}
__device__ __forceinline__ void upk2(u64 v, float& lo, float& hi) {
    unsigned a, b;
    asm("mov.b64 {%0, %1}, %2;" : "=r"(a), "=r"(b) : "l"(v));
    lo = __uint_as_float(a); hi = __uint_as_float(b);
}
__device__ __forceinline__ u64 fma2(u64 a, u64 b, u64 c) {
    u64 d;
    asm("fma.rn.f32x2 %0, %1, %2, %3;" : "=l"(d) : "l"(a), "l"(b), "l"(c));
    return d;
}

// ---- fp16 pack: result = {lo16 = lo_val, hi16 = hi_val} ----
__device__ __forceinline__ u32 pkhf(float lo_val, float hi_val) {
    u32 d;
    asm("cvt.rn.f16x2.f32 %0, %1, %2;" : "=r"(d) : "f"(hi_val), "f"(lo_val));
    return d;
}

// ---- fp16 mma m16n8k16 ----
__device__ __forceinline__ void mma_f16(float d[4], const u32 a[4], u32 b0, u32 b1) {
    asm volatile(
        "mma.sync.aligned.m16n8k16.row.col.f32.f16.f16.f32 "
        "{%0,%1,%2,%3}, {%4,%5,%6,%7}, {%8,%9}, {%0,%1,%2,%3};"
        : "+f"(d[0]), "+f"(d[1]), "+f"(d[2]), "+f"(d[3])
        : "r"(a[0]), "r"(a[1]), "r"(a[2]), "r"(a[3]), "r"(b0), "r"(b1));
}

#define QSTR 24    // u16 per Q/K smem row (16 data + 8 pad) -> 48B stride; fragment LDS
                   // banks: (gID*12 + tig) % 32 all-distinct across the warp
#define VSTR 136   // u16 per Vt row (128 data + 8 pad) -> 272B stride, bank-clean

// ============================================================
// fp16 mma.sync flash attention (no max subtraction; logits small).
// grid (S/128, B*H), 256 threads = 8 warps x 16 query rows.
// ============================================================
__global__ void __launch_bounds__(256) attn_mma_kernel()
{
    __shared__ u16 Qs[128][QSTR];      // 6144 B
    __shared__ u16 Ks[128][QSTR];      // 6144 B
    __shared__ u16 Vt[16][VSTR];       // 4352 B
    __shared__ float red[128 * 17];    // 8704 B

    const int tid  = threadIdx.x;
    const int lane = tid & 31;
    const int warp = tid >> 5;
    const int gID  = lane >> 2;
    const int tig  = lane & 3;
    const int bh   = blockIdx.y;
    const int q0   = blockIdx.x * 128;

    // ---- Q tile: 16B copies (row = 2 uint4) ----
    {
        const int r    = tid >> 1;
        const int part = tid & 1;
        const uint4 v = *(const uint4*)&g_qs[((size_t)bh * S_ + q0 + r) * 16 + part * 8];
        *(uint4*)&Qs[r][part * 8] = v;
    }
    __syncthreads();

    // ---- Q A-fragments ----
    u32 qa[4];
    {
        const int ra = warp * 16 + gID;
        qa[0] = *(const u32*)&Qs[ra][2 * tig];
        qa[1] = *(const u32*)&Qs[ra + 8][2 * tig];
        qa[2] = *(const u32*)&Qs[ra][2 * tig + 8];
        qa[3] = *(const u32*)&Qs[ra + 8][2 * tig + 8];
    }

    float out0[4] = {0.f, 0.f, 0.f, 0.f};
    float out1[4] = {0.f, 0.f, 0.f, 0.f};
    float ls0 = 0.f, ls1 = 0.f;

    for (int t = 0; t < S_ / 128; t++) {
        __syncthreads();
        // ---- K tile ----
        {
            const int r    = tid >> 1;
            const int part = tid & 1;
            const uint4 v = *(const uint4*)&g_ks[((size_t)bh * S_ + t * 128 + r) * 16 + part * 8];
            *(uint4*)&Ks[r][part * 8] = v;
        }
        // ---- V tile (already transposed) ----
        {
            const int dk  = tid >> 4;
            const int off = tid & 15;
            const size_t gi = ((size_t)bh * 16 + dk) * S_ + t * 128 + off * 8;
            *(uint4*)&Vt[dk][off * 8] = *(const uint4*)&g_vt[gi];
        }
        __syncthreads();

        #pragma unroll
        for (int half = 0; half < 2; half++) {
            u32 pa[8], pb[8];

            // ---- QK scores for 8 n-tiles (64 keys), exp, pack fp16 ----
            #pragma unroll
            for (int j = 0; j < 8; j++) {
                const int kn = half * 64 + j * 8 + gID;
                const u32 b0 = *(const u32*)&Ks[kn][2 * tig];
                const u32 b1 = *(const u32*)&Ks[kn][2 * tig + 8];
                float d[4] = {0.f, 0.f, 0.f, 0.f};
                mma_f16(d, qa, b0, b1);

                const float p0 = __expf(d[0]);
                const float p1 = __expf(d[1]);
                const float p2 = __expf(d[2]);
                const float p3 = __expf(d[3]);
                ls0 += p0 + p1;
                ls1 += p2 + p3;
                pa[j] = pkhf(p0, p1);
                pb[j] = pkhf(p2, p3);
            }

            // ---- PV: 4 k-steps of 16 keys ----
            #pragma unroll
            for (int ks = 0; ks < 4; ks++) {
                const u32 A[4] = {pa[2 * ks], pb[2 * ks], pa[2 * ks + 1], pb[2 * ks + 1]};
                const int kb2 = half * 64 + ks * 16 + 2 * tig;
                {
                    const int dr = gID;
                    const u32 v0 = *(const u32*)&Vt[dr][kb2];
                    const u32 v1 = *(const u32*)&Vt[dr][kb2 + 8];
                    mma_f16(out0, A, v0, v1);
                }
                {
                    const int dr = 8 + gID;
                    const u32 v0 = *(const u32*)&Vt[dr][kb2];
                    const u32 v1 = *(const u32*)&Vt[dr][kb2 + 8];
                    mma_f16(out1, A, v0, v1);
                }
            }
        }
    }

    // ---- row sums across quad ----
    ls0 += __shfl_xor_sync(0xFFFFFFFFu, ls0, 1);
    ls0 += __shfl_xor_sync(0xFFFFFFFFu, ls0, 2);
    ls1 += __shfl_xor_sync(0xFFFFFFFFu, ls1, 1);
    ls1 += __shfl_xor_sync(0xFFFFFFFFu, ls1, 2);
    const float i0 = 1.f / ls0;
    const float i1 = 1.f / ls1;

    __syncthreads();
    {
        const int ra = warp * 16 + gID;
        const int c0 = 2 * tig;
        red[ra * 17 + c0 + 0]       = out0[0] * i0;
        red[ra * 17 + c0 + 1]       = out0[1] * i0;
        red[(ra + 8) * 17 + c0 + 0] = out0[2] * i1;
        red[(ra + 8) * 17 + c0 + 1] = out0[3] * i1;
        red[ra * 17 + 8 + c0 + 0]       = out1[0] * i0;
        red[ra * 17 + 8 + c0 + 1]       = out1[1] * i0;
        red[(ra + 8) * 17 + 8 + c0 + 0] = out1[2] * i1;
        red[(ra + 8) * 17 + 8 + c0 + 1] = out1[3] * i1;
    }
    __syncthreads();

    float* part = (float*)&Qs[0][0];   // 1KB scratch
    {
        const int c  = tid & 15;
        const int r0 = tid >> 4;
        float m = red[r0 * 17 + c];
        #pragma unroll
        for (int i = 1; i < 8; i++)
            m = fmaxf(m, red[(r0 + 16 * i) * 17 + c]);
        part[r0 * 16 + c] = m;
    }
    __syncthreads();
    if (tid < 16) {
        float m = part[tid];
        #pragma unroll
        for (int r = 1; r < 16; r++)
            m = fmaxf(m, part[r * 16 + tid]);
        const int b = bh >> 3, h = bh & 7;
        atomicMax(&g_max[b * D_ + h * DK_ + tid], fkey(m));
    }
}

// ============================================================
// Fused 2-layer MLP (f32x2); epilogue writes fp16.
// ============================================================
__global__ void __launch_bounds__(256) qkv_mlp_kernel(
    const float* __restrict__ x,
    const float* __restrict__ qW1, const float* __restrict__ qb1,
    const float* __restrict__ qW2, const float* __restrict__ qb2,
    const float* __restrict__ kW1, const float* __restrict__ kb1,
    const float* __restrict__ kW2, const float* __restrict__ kb2,
    const float* __restrict__ vW1, const float* __restrict__ vb1,
    const float* __restrict__ vW2, const float* __restrict__ vb2)
{
    const int tid = threadIdx.x;
    const int mlp = blockIdx.y;

    const float *W1, *b1, *W2, *b2;
    if (mlp == 0)      { W1 = qW1; b1 = qb1; W2 = qW2; b2 = qb2; }
    else if (mlp == 1) { W1 = kW1; b1 = kb1; W2 = kW2; b2 = kb2; }
    else               { W1 = vW1; b1 = vb1; W2 = vW2; b2 = vb2; }

    const int tok0 = blockIdx.x * TOK;

    __shared__ float xs[F_ * XSTR];
    __shared__ float hsm[HID_ * XSTR];

    {
        const float4* xg = (const float4*)(x + tok0 * F_);
        #pragma unroll
        for (int r = 0; r < 2; r++) {
            const int g  = tid + r * 256;
            const int t  = g >> 4;
            const int fb = (g & 15) * 4;
            const float4 v = xg[g];
            xs[(fb + 0) * XSTR + t] = v.x;
            xs[(fb + 1) * XSTR + t] = v.y;
            xs[(fb + 2) * XSTR + t] = v.z;
            xs[(fb + 3) * XSTR + t] = v.w;
        }
    }
    __syncthreads();

    {
        u64 acc[16];
        #pragma unroll
        for (int e = 0; e < 16; e++) acc[e] = 0ull;

        #pragma unroll 4
        for (int i = 0; i < F_; i++) {
            const float w = __ldg(&W1[i * HID_ + tid]);
            const u64 wb = pk2(w, w);
            const ulonglong2* xr = (const ulonglong2*)(xs + i * XSTR);
            #pragma unroll
            for (int u = 0; u < 8; u++) {
                const ulonglong2 xp = xr[u];
                acc[2 * u + 0] = fma2(wb, xp.x, acc[2 * u + 0]);
                acc[2 * u + 1] = fma2(wb, xp.y, acc[2 * u + 1]);
            }
        }
        const float bb = b1[tid];
        #pragma unroll
        for (int e = 0; e < 16; e++) {
            float a, b;
            upk2(acc[e], a, b);
            a += bb; b += bb;
            hsm[tid * XSTR + 2 * e + 0] = (a > 0.f) ? a : (__expf(a) - 1.f);
            hsm[tid * XSTR + 2 * e + 1] = (b > 0.f) ? b : (__expf(b) - 1.f);
        }
    }
    __syncthreads();

    {
        const int j  = tid & 127;
        const int tg = tid >> 7;
        u64 acc[8];
        #pragma unroll
        for (int e = 0; e < 8; e++) acc[e] = 0ull;

        #pragma unroll 4
        for (int i = 0; i < HID_; i++) {
            const float w = __ldg(&W2[i * D_ + j]);
            const u64 wb = pk2(w, w);
            const ulonglong2* hr = (const ulonglong2*)(hsm + i * XSTR + tg * 16);
            #pragma unroll
            for (int u = 0; u < 4; u++) {
                const ulonglong2 hp = hr[u];
                acc[2 * u + 0] = fma2(wb, hp.x, acc[2 * u + 0]);
                acc[2 * u + 1] = fma2(wb, hp.y, acc[2 * u + 1]);
            }
        }
        const float bb = b2[j];
        const int h   = j >> 4;
        const int dkc = j & 15;
        #pragma unroll
        for (int e = 0; e < 8; e++) {
            float a, b;
            upk2(acc[e], a, b);
            float va = a + bb, vb = b + bb;
            if (mlp == 0) { va *= 0.25f; vb *= 0.25f; }
            const u16 hA = __half_as_ushort(__float2half_rn(va));
            const u16 hB = __half_as_ushort(__float2half_rn(vb));

            const int tokA = tok0 + tg * 16 + 2 * e;
            const int bA   = tokA >> 11;
            const int sA   = tokA & (S_ - 1);
            const int bhD  = bA * H_ + h;
            if (mlp < 2) {
                u16* base = (mlp == 0) ? g_qs : g_ks;
                const size_t r0 = ((size_t)bhD * S_ + sA) * 16;
                base[r0 + dkc]      = hA;
                base[r0 + 16 + dkc] = hB;      // token sA+1
            } else {
                const size_t vi = ((size_t)bhD * 16 + dkc) * S_ + sA;
                g_vt[vi]     = hA;
                g_vt[vi + 1] = hB;
            }
        }
    }
}

extern "C" void kernel_launch(void* const* d_in, const int* in_sizes, int n_in,
                              void* d_out, int out_size)
{
    const float* x   = (const float*)d_in[0];
    const float* qW1 = (const float*)d_in[1];
    const float* qb1 = (const float*)d_in[2];
    const float* qW2 = (const float*)d_in[3];
    const float* qb2 = (const float*)d_in[4];
    const float* kW1 = (const float*)d_in[5];
    const float* kb1 = (const float*)d_in[6];
    const float* kW2 = (const float*)d_in[7];
    const float* kb2 = (const float*)d_in[8];
    const float* vW1 = (const float*)d_in[9];
    const float* vb1 = (const float*)d_in[10];
    const float* vW2 = (const float*)d_in[11];
    const float* vb2 = (const float*)d_in[12];

    init_kernel<<<1, B_ * D_>>>();

    dim3 gmlp(B_ * S_ / TOK, 3);
    qkv_mlp_kernel<<<gmlp, 256>>>(x, qW1, qb1, qW2, qb2,
                                     kW1, kb1, kW2, kb2,
                                     vW1, vb1, vW2, vb2);

    dim3 gatt(S_ / 128, B_ * H_);
    attn_mma_kernel<<<gatt, 256>>>();

    finalize_kernel<<<1, B_ * D_>>>((float*)d_out);
}

// round 7
// speedup vs baseline: 4.1566x; 1.3891x over previous
#include <cuda_runtime.h>
#include <cuda_fp16.h>
#include <cstdint>

#define B_   4
#define S_   2048
#define F_   64
#define HID_ 256
#define D_   128
#define H_   8
#define DK_  16

typedef unsigned long long u64;
typedef unsigned int u32;
typedef unsigned short u16;

// fp16 operands for attention:
//  g_qs/g_ks: [bh][s][16]  (Q pre-scaled by 0.25)
//  g_vt:      [bh][dk][s]  (V transposed)
__device__ __align__(16) u16 g_qs[B_ * H_ * S_ * 16];
__device__ __align__(16) u16 g_ks[B_ * H_ * S_ * 16];
__device__ __align__(16) u16 g_vt[B_ * H_ * 16 * S_];
__device__ unsigned g_max[B_ * D_];

// fp16-pair packed weights: W1p[mlp][n=256][kp=32], W2p[mlp][n=128][kp=128]
__device__ u32 g_w1p[3 * 256 * 32];
__device__ u32 g_w2p[3 * 128 * 128];

// ---- order-preserving float <-> uint keys for atomicMax ----
__device__ __forceinline__ unsigned fkey(float f) {
    unsigned u = __float_as_uint(f);
    return (u & 0x80000000u) ? ~u : (u | 0x80000000u);
}
__device__ __forceinline__ float ikey(unsigned k) {
    unsigned u = (k & 0x80000000u) ? (k & 0x7FFFFFFFu) : ~k;
    return __uint_as_float(u);
}

__global__ void init_kernel() { g_max[threadIdx.x] = 0u; }
__global__ void finalize_kernel(float* __restrict__ out) {
    out[threadIdx.x] = ikey(g_max[threadIdx.x]);
}

// ---- fp16 pack: u32 = {lo16 = lo_val, hi16 = hi_val} ----
__device__ __forceinline__ u32 pkhf(float lo_val, float hi_val) {
    u32 d;
    asm("cvt.rn.f16x2.f32 %0, %1, %2;" : "=r"(d) : "f"(hi_val), "f"(lo_val));
    return d;
}

// ---- fp16 mma m16n8k16 ----
__device__ __forceinline__ void mma_f16(float d[4], const u32 a[4], u32 b0, u32 b1) {
    asm volatile(
        "mma.sync.aligned.m16n8k16.row.col.f32.f16.f16.f32 "
        "{%0,%1,%2,%3}, {%4,%5,%6,%7}, {%8,%9}, {%0,%1,%2,%3};"
        : "+f"(d[0]), "+f"(d[1]), "+f"(d[2]), "+f"(d[3])
        : "r"(a[0]), "r"(a[1]), "r"(a[2]), "r"(a[3]), "r"(b0), "r"(b1));
}

// ============================================================
// Weight packer: fragment-friendly fp16-pair layout, once per launch.
// ============================================================
__global__ void __launch_bounds__(256) pack_weights_kernel(
    const float* __restrict__ qW1, const float* __restrict__ kW1, const float* __restrict__ vW1,
    const float* __restrict__ qW2, const float* __restrict__ kW2, const float* __restrict__ vW2)
{
    const int i = blockIdx.x * 256 + threadIdx.x;
    if (i < 3 * 256 * 32) {
        const int mlp = i / (256 * 32);
        const int r   = i % (256 * 32);
        const int n   = r >> 5;
        const int kp  = r & 31;
        const float* W = (mlp == 0) ? qW1 : (mlp == 1) ? kW1 : vW1;
        g_w1p[i] = pkhf(W[(2 * kp) * HID_ + n], W[(2 * kp + 1) * HID_ + n]);
    }
    if (i < 3 * 128 * 128) {
        const int mlp = i / (128 * 128);
        const int r   = i % (128 * 128);
        const int n   = r >> 7;
        const int kp  = r & 127;
        const float* W = (mlp == 0) ? qW2 : (mlp == 1) ? kW2 : vW2;
        g_w2p[i] = pkhf(W[(2 * kp) * D_ + n], W[(2 * kp + 1) * D_ + n]);
    }
}

// ============================================================
// Tensor-core MLP: block = 64 tokens, 8 warps = 4 tok-groups x 2 col-halves.
// grid (8192/64, 3).
// ============================================================
__global__ void __launch_bounds__(256) mlp_mma_kernel(
    const float* __restrict__ x,
    const float* __restrict__ qb1, const float* __restrict__ qb2,
    const float* __restrict__ kb1, const float* __restrict__ kb2,
    const float* __restrict__ vb1, const float* __restrict__ vb2)
{
    __shared__ u32 xs[64][36];     //  9216 B  (fp16 pairs, [tok][kp])
    __shared__ u32 hsm[64][132];   // 33792 B  (fp16 pairs, [tok][kp])

    const int tid  = threadIdx.x;
    const int lane = tid & 31;
    const int warp = tid >> 5;
    const int gID  = lane >> 2;
    const int tig  = lane & 3;
    const int mlp  = blockIdx.y;
    const int tok0 = blockIdx.x * 64;

    const float* b1v = (mlp == 0) ? qb1 : (mlp == 1) ? kb1 : vb1;
    const float* b2v = (mlp == 0) ? qb2 : (mlp == 1) ? kb2 : vb2;

    // ---- load x tile, convert to fp16 pairs ----
    {
        const float4* xg = (const float4*)(x + (size_t)tok0 * F_);
        #pragma unroll
        for (int r = 0; r < 4; r++) {
            const int g   = tid + r * 256;      // float4 index
            const int tok = g >> 4;
            const int f4  = g & 15;
            const float4 v = xg[g];
            xs[tok][f4 * 2 + 0] = pkhf(v.x, v.y);
            xs[tok][f4 * 2 + 1] = pkhf(v.z, v.w);
        }
    }
    __syncthreads();

    const int tg = warp >> 1;
    const int nh = warp & 1;
    const int ra = tg * 16 + gID;

    // ---- Layer 1: h = elu(x @ W1 + b1), 16 n-tiles x 4 k-steps ----
    float acc[16][4];
    #pragma unroll
    for (int j = 0; j < 16; j++)
        #pragma unroll
        for (int e = 0; e < 4; e++) acc[j][e] = 0.f;

    {
        const u32* wb = g_w1p + mlp * (256 * 32);
        #pragma unroll
        for (int ks = 0; ks < 4; ks++) {
            u32 a[4];
            a[0] = xs[ra][8 * ks + tig];
            a[1] = xs[ra + 8][8 * ks + tig];
            a[2] = xs[ra][8 * ks + tig + 4];
            a[3] = xs[ra + 8][8 * ks + tig + 4];
            #pragma unroll
            for (int j = 0; j < 16; j++) {
                const int n = nh * 128 + j * 8 + gID;
                const u32 b0 = __ldg(&wb[n * 32 + 8 * ks + tig]);
                const u32 b1 = __ldg(&wb[n * 32 + 8 * ks + tig + 4]);
                mma_f16(acc[j], a, b0, b1);
            }
        }
    }

    #pragma unroll
    for (int j = 0; j < 16; j++) {
        const int c0 = nh * 128 + j * 8 + 2 * tig;
        const float bb0 = b1v[c0], bb1 = b1v[c0 + 1];
        float e0 = acc[j][0] + bb0, e1 = acc[j][1] + bb1;
        float e2 = acc[j][2] + bb0, e3 = acc[j][3] + bb1;
        e0 = (e0 > 0.f) ? e0 : (__expf(e0) - 1.f);
        e1 = (e1 > 0.f) ? e1 : (__expf(e1) - 1.f);
        e2 = (e2 > 0.f) ? e2 : (__expf(e2) - 1.f);
        e3 = (e3 > 0.f) ? e3 : (__expf(e3) - 1.f);
        hsm[ra][nh * 64 + 4 * j + tig]     = pkhf(e0, e1);
        hsm[ra + 8][nh * 64 + 4 * j + tig] = pkhf(e2, e3);
    }
    __syncthreads();

    // ---- Layer 2: out = h @ W2 + b2, 8 n-tiles x 16 k-steps ----
    float out[8][4];
    #pragma unroll
    for (int j = 0; j < 8; j++)
        #pragma unroll
        for (int e = 0; e < 4; e++) out[j][e] = 0.f;

    {
        const u32* wb = g_w2p + mlp * (128 * 128);
        #pragma unroll
        for (int ks = 0; ks < 16; ks++) {
            u32 a[4];
            a[0] = hsm[ra][8 * ks + tig];
            a[1] = hsm[ra + 8][8 * ks + tig];
            a[2] = hsm[ra][8 * ks + tig + 4];
            a[3] = hsm[ra + 8][8 * ks + tig + 4];
            #pragma unroll
            for (int j = 0; j < 8; j++) {
                const int n = nh * 64 + j * 8 + gID;
                const u32 b0 = __ldg(&wb[n * 128 + 8 * ks + tig]);
                const u32 b1 = __ldg(&wb[n * 128 + 8 * ks + tig + 4]);
                mma_f16(out[j], a, b0, b1);
            }
        }
    }

    // ---- epilogue: bias, scale(Q), cvt fp16, scatter ----
    const float qsc = (mlp == 0) ? 0.25f : 1.0f;
    #pragma unroll
    for (int j = 0; j < 8; j++) {
        const int c0 = nh * 64 + j * 8 + 2 * tig;   // even, c0+1 same head
        const float bb0 = b2v[c0], bb1 = b2v[c0 + 1];
        const float v00 = (out[j][0] + bb0) * qsc;
        const float v01 = (out[j][1] + bb1) * qsc;
        const float v10 = (out[j][2] + bb0) * qsc;
        const float v11 = (out[j][3] + bb1) * qsc;
        const u32 pr = pkhf(v00, v01);   // row ra
        const u32 ps = pkhf(v10, v11);   // row ra+8

        const int h   = c0 >> 4;
        const int dk0 = c0 & 15;
        const int tokA = tok0 + ra;
        const int bA = tokA >> 11, sA = tokA & (S_ - 1);
        const int tokB = tokA + 8;
        const int bB = tokB >> 11, sB = tokB & (S_ - 1);
        const int bhA = bA * H_ + h, bhB = bB * H_ + h;

        if (mlp < 2) {
            u16* base = (mlp == 0) ? g_qs : g_ks;
            *(u32*)&base[((size_t)bhA * S_ + sA) * 16 + dk0] = pr;
            *(u32*)&base[((size_t)bhB * S_ + sB) * 16 + dk0] = ps;
        } else {
            g_vt[((size_t)bhA * 16 + dk0) * S_ + sA]     = (u16)(pr & 0xFFFF);
            g_vt[((size_t)bhA * 16 + dk0 + 1) * S_ + sA] = (u16)(pr >> 16);
            g_vt[((size_t)bhB * 16 + dk0) * S_ + sB]     = (u16)(ps & 0xFFFF);
            g_vt[((size_t)bhB * 16 + dk0 + 1) * S_ + sB] = (u16)(ps >> 16);
        }
    }
}

#define QSTR 24    // u16 per Q/K smem row -> 48B stride, fragment LDS bank-clean
#define VSTR 136   // u16 per Vt row -> 272B stride, bank-clean

// ============================================================
// fp16 mma.sync flash attention (no max subtraction; logits small).
// grid (S/128, B*H), 256 threads = 8 warps x 16 query rows.
// ============================================================
__global__ void __launch_bounds__(256) attn_mma_kernel()
{
    __shared__ u16 Qs[128][QSTR];
    __shared__ u16 Ks[128][QSTR];
    __shared__ u16 Vt[16][VSTR];
    __shared__ float red[128 * 17];

    const int tid  = threadIdx.x;
    const int lane = tid & 31;
    const int warp = tid >> 5;
    const int gID  = lane >> 2;
    const int tig  = lane & 3;
    const int bh   = blockIdx.y;
    const int q0   = blockIdx.x * 128;

    {
        const int r    = tid >> 1;
        const int part = tid & 1;
        const uint4 v = *(const uint4*)&g_qs[((size_t)bh * S_ + q0 + r) * 16 + part * 8];
        *(uint4*)&Qs[r][part * 8] = v;
    }
    __syncthreads();

    u32 qa[4];
    {
        const int ra = warp * 16 + gID;
        qa[0] = *(const u32*)&Qs[ra][2 * tig];
        qa[1] = *(const u32*)&Qs[ra + 8][2 * tig];
        qa[2] = *(const u32*)&Qs[ra][2 * tig + 8];
        qa[3] = *(const u32*)&Qs[ra + 8][2 * tig + 8];
    }

    float out0[4] = {0.f, 0.f, 0.f, 0.f};
    float out1[4] = {0.f, 0.f, 0.f, 0.f};
    float ls0 = 0.f, ls1 = 0.f;

    for (int t = 0; t < S_ / 128; t++) {
        __syncthreads();
        {
            const int r    = tid >> 1;
            const int part = tid & 1;
            const uint4 v = *(const uint4*)&g_ks[((size_t)bh * S_ + t * 128 + r) * 16 + part * 8];
            *(uint4*)&Ks[r][part * 8] = v;
        }
        {
            const int dk  = tid >> 4;
            const int off = tid & 15;
            const size_t gi = ((size_t)bh * 16 + dk) * S_ + t * 128 + off * 8;
            *(uint4*)&Vt[dk][off * 8] = *(const uint4*)&g_vt[gi];
        }
        __syncthreads();

        #pragma unroll
        for (int half = 0; half < 2; half++) {
            u32 pa[8], pb[8];

            #pragma unroll
            for (int j = 0; j < 8; j++) {
                const int kn = half * 64 + j * 8 + gID;
                const u32 b0 = *(const u32*)&Ks[kn][2 * tig];
                const u32 b1 = *(const u32*)&Ks[kn][2 * tig + 8];
                float d[4] = {0.f, 0.f, 0.f, 0.f};
                mma_f16(d, qa, b0, b1);

                const float p0 = __expf(d[0]);
                const float p1 = __expf(d[1]);
                const float p2 = __expf(d[2]);
                const float p3 = __expf(d[3]);
                ls0 += p0 + p1;
                ls1 += p2 + p3;
                pa[j] = pkhf(p0, p1);
                pb[j] = pkhf(p2, p3);
            }

            #pragma unroll
            for (int ks = 0; ks < 4; ks++) {
                const u32 A[4] = {pa[2 * ks], pb[2 * ks], pa[2 * ks + 1], pb[2 * ks + 1]};
                const int kb2 = half * 64 + ks * 16 + 2 * tig;
                {
                    const u32 v0 = *(const u32*)&Vt[gID][kb2];
                    const u32 v1 = *(const u32*)&Vt[gID][kb2 + 8];
                    mma_f16(out0, A, v0, v1);
                }
                {
                    const u32 v0 = *(const u32*)&Vt[8 + gID][kb2];
                    const u32 v1 = *(const u32*)&Vt[8 + gID][kb2 + 8];
                    mma_f16(out1, A, v0, v1);
                }
            }
        }
    }

    ls0 += __shfl_xor_sync(0xFFFFFFFFu, ls0, 1);
    ls0 += __shfl_xor_sync(0xFFFFFFFFu, ls0, 2);
    ls1 += __shfl_xor_sync(0xFFFFFFFFu, ls1, 1);
    ls1 += __shfl_xor_sync(0xFFFFFFFFu, ls1, 2);
    const float i0 = 1.f / ls0;
    const float i1 = 1.f / ls1;

    __syncthreads();
    {
        const int ra = warp * 16 + gID;
        const int c0 = 2 * tig;
        red[ra * 17 + c0 + 0]       = out0[0] * i0;
        red[ra * 17 + c0 + 1]       = out0[1] * i0;
        red[(ra + 8) * 17 + c0 + 0] = out0[2] * i1;
        red[(ra + 8) * 17 + c0 + 1] = out0[3] * i1;
        red[ra * 17 + 8 + c0 + 0]       = out1[0] * i0;
        red[ra * 17 + 8 + c0 + 1]       = out1[1] * i0;
        red[(ra + 8) * 17 + 8 + c0 + 0] = out1[2] * i1;
        red[(ra + 8) * 17 + 8 + c0 + 1] = out1[3] * i1;
    }
    __syncthreads();

    float* part = (float*)&Qs[0][0];
    {
        const int c  = tid & 15;
        const int r0 = tid >> 4;
        float m = red[r0 * 17 + c];
        #pragma unroll
        for (int i = 1; i < 8; i++)
            m = fmaxf(m, red[(r0 + 16 * i) * 17 + c]);
        part[r0 * 16 + c] = m;
    }
    __syncthreads();
    if (tid < 16) {
        float m = part[tid];
        #pragma unroll
        for (int r = 1; r < 16; r++)
            m = fmaxf(m, part[r * 16 + tid]);
        const int b = bh >> 3, h = bh & 7;
        atomicMax(&g_max[b * D_ + h * DK_ + tid], fkey(m));
    }
}

extern "C" void kernel_launch(void* const* d_in, const int* in_sizes, int n_in,
                              void* d_out, int out_size)
{
    const float* x   = (const float*)d_in[0];
    const float* qW1 = (const float*)d_in[1];
    const float* qb1 = (const float*)d_in[2];
    const float* qW2 = (const float*)d_in[3];
    const float* qb2 = (const float*)d_in[4];
    const float* kW1 = (const float*)d_in[5];
    const float* kb1 = (const float*)d_in[6];
    const float* kW2 = (const float*)d_in[7];
    const float* kb2 = (const float*)d_in[8];
    const float* vW1 = (const float*)d_in[9];
    const float* vb1 = (const float*)d_in[10];
    const float* vW2 = (const float*)d_in[11];
    const float* vb2 = (const float*)d_in[12];

    init_kernel<<<1, B_ * D_>>>();
    pack_weights_kernel<<<192, 256>>>(qW1, kW1, vW1, qW2, kW2, vW2);

    dim3 gmlp(B_ * S_ / 64, 3);
    mlp_mma_kernel<<<gmlp, 256>>>(x, qb1, qb2, kb1, kb2, vb1, vb2);

    dim3 gatt(S_ / 128, B_ * H_);
    attn_mma_kernel<<<gatt, 256>>>();

    finalize_kernel<<<1, B_ * D_>>>((float*)d_out);
}

// round 8
// speedup vs baseline: 5.0915x; 1.2249x over previous
#include <cuda_runtime.h>
#include <cuda_fp16.h>
#include <cstdint>

#define B_   4
#define S_   2048
#define F_   64
#define HID_ 256
#define D_   128
#define H_   8
#define DK_  16

typedef unsigned long long u64;
typedef unsigned int u32;
typedef unsigned short u16;

// fp16 operands for attention:
//  g_qs/g_ks: [bh][s][16]  (Q pre-scaled by 0.25*log2e)
//  g_vt:      [bh][dk][s]  (V transposed)
__device__ __align__(16) u16 g_qs[B_ * H_ * S_ * 16];
__device__ __align__(16) u16 g_ks[B_ * H_ * S_ * 16];
__device__ __align__(16) u16 g_vt[B_ * H_ * 16 * S_];
__device__ unsigned g_max[B_ * D_];

// fp16-pair packed weights: W1p[mlp][n=256][kp=32], W2p[mlp][n=128][kp=128]
__device__ u32 g_w1p[3 * 256 * 32];
__device__ u32 g_w2p[3 * 128 * 128];

// ---- order-preserving float <-> uint keys for atomicMax ----
__device__ __forceinline__ unsigned fkey(float f) {
    unsigned u = __float_as_uint(f);
    return (u & 0x80000000u) ? ~u : (u | 0x80000000u);
}
__device__ __forceinline__ float ikey(unsigned k) {
    unsigned u = (k & 0x80000000u) ? (k & 0x7FFFFFFFu) : ~k;
    return __uint_as_float(u);
}

__global__ void finalize_kernel(float* __restrict__ out) {
    out[threadIdx.x] = ikey(g_max[threadIdx.x]);
}

// ---- fp16 pack: u32 = {lo16 = lo_val, hi16 = hi_val} ----
__device__ __forceinline__ u32 pkhf(float lo_val, float hi_val) {
    u32 d;
    asm("cvt.rn.f16x2.f32 %0, %1, %2;" : "=r"(d) : "f"(hi_val), "f"(lo_val));
    return d;
}
// ---- packed fp16 exp2 ----
__device__ __forceinline__ u32 ex2h2(u32 x) {
    u32 d;
    asm("ex2.approx.f16x2 %0, %1;" : "=r"(d) : "r"(x));
    return d;
}

// ---- fp16 mma m16n8k16 ----
__device__ __forceinline__ void mma_f16(float d[4], const u32 a[4], u32 b0, u32 b1) {
    asm volatile(
        "mma.sync.aligned.m16n8k16.row.col.f32.f16.f16.f32 "
        "{%0,%1,%2,%3}, {%4,%5,%6,%7}, {%8,%9}, {%0,%1,%2,%3};"
        : "+f"(d[0]), "+f"(d[1]), "+f"(d[2]), "+f"(d[3])
        : "r"(a[0]), "r"(a[1]), "r"(a[2]), "r"(a[3]), "r"(b0), "r"(b1));
}

// ============================================================
// Weight packer + g_max init, once per launch.
// ============================================================
__global__ void __launch_bounds__(256) pack_weights_kernel(
    const float* __restrict__ qW1, const float* __restrict__ kW1, const float* __restrict__ vW1,
    const float* __restrict__ qW2, const float* __restrict__ kW2, const float* __restrict__ vW2)
{
    const int i = blockIdx.x * 256 + threadIdx.x;
    if (i < B_ * D_) g_max[i] = 0u;
    if (i < 3 * 256 * 32) {
        const int mlp = i / (256 * 32);
        const int r   = i % (256 * 32);
        const int n   = r >> 5;
        const int kp  = r & 31;
        const float* W = (mlp == 0) ? qW1 : (mlp == 1) ? kW1 : vW1;
        g_w1p[i] = pkhf(W[(2 * kp) * HID_ + n], W[(2 * kp + 1) * HID_ + n]);
    }
    if (i < 3 * 128 * 128) {
        const int mlp = i / (128 * 128);
        const int r   = i % (128 * 128);
        const int n   = r >> 7;
        const int kp  = r & 127;
        const float* W = (mlp == 0) ? qW2 : (mlp == 1) ? kW2 : vW2;
        g_w2p[i] = pkhf(W[(2 * kp) * D_ + n], W[(2 * kp + 1) * D_ + n]);
    }
}

// ============================================================
// Tensor-core MLP: block = 64 tokens, 8 warps = 4 tok-groups x 2 col-halves.
// grid (8192/64, 3).
// ============================================================
__global__ void __launch_bounds__(256) mlp_mma_kernel(
    const float* __restrict__ x,
    const float* __restrict__ qb1, const float* __restrict__ qb2,
    const float* __restrict__ kb1, const float* __restrict__ kb2,
    const float* __restrict__ vb1, const float* __restrict__ vb2)
{
    __shared__ u32 xs[64][36];
    __shared__ u32 hsm[64][132];

    const int tid  = threadIdx.x;
    const int lane = tid & 31;
    const int warp = tid >> 5;
    const int gID  = lane >> 2;
    const int tig  = lane & 3;
    const int mlp  = blockIdx.y;
    const int tok0 = blockIdx.x * 64;

    const float* b1v = (mlp == 0) ? qb1 : (mlp == 1) ? kb1 : vb1;
    const float* b2v = (mlp == 0) ? qb2 : (mlp == 1) ? kb2 : vb2;

    {
        const float4* xg = (const float4*)(x + (size_t)tok0 * F_);
        #pragma unroll
        for (int r = 0; r < 4; r++) {
            const int g   = tid + r * 256;
            const int tok = g >> 4;
            const int f4  = g & 15;
            const float4 v = xg[g];
            xs[tok][f4 * 2 + 0] = pkhf(v.x, v.y);
            xs[tok][f4 * 2 + 1] = pkhf(v.z, v.w);
        }
    }
    __syncthreads();

    const int tg = warp >> 1;
    const int nh = warp & 1;
    const int ra = tg * 16 + gID;

    // ---- Layer 1 ----
    float acc[16][4];
    #pragma unroll
    for (int j = 0; j < 16; j++)
        #pragma unroll
        for (int e = 0; e < 4; e++) acc[j][e] = 0.f;

    {
        const u32* wb = g_w1p + mlp * (256 * 32);
        #pragma unroll
        for (int ks = 0; ks < 4; ks++) {
            u32 a[4];
            a[0] = xs[ra][8 * ks + tig];
            a[1] = xs[ra + 8][8 * ks + tig];
            a[2] = xs[ra][8 * ks + tig + 4];
            a[3] = xs[ra + 8][8 * ks + tig + 4];
            #pragma unroll
            for (int j = 0; j < 16; j++) {
                const int n = nh * 128 + j * 8 + gID;
                const u32 b0 = __ldg(&wb[n * 32 + 8 * ks + tig]);
                const u32 b1 = __ldg(&wb[n * 32 + 8 * ks + tig + 4]);
                mma_f16(acc[j], a, b0, b1);
            }
        }
    }

    #pragma unroll
    for (int j = 0; j < 16; j++) {
        const int c0 = nh * 128 + j * 8 + 2 * tig;
        const float bb0 = b1v[c0], bb1 = b1v[c0 + 1];
        float e0 = acc[j][0] + bb0, e1 = acc[j][1] + bb1;
        float e2 = acc[j][2] + bb0, e3 = acc[j][3] + bb1;
        e0 = (e0 > 0.f) ? e0 : (__expf(e0) - 1.f);
        e1 = (e1 > 0.f) ? e1 : (__expf(e1) - 1.f);
        e2 = (e2 > 0.f) ? e2 : (__expf(e2) - 1.f);
        e3 = (e3 > 0.f) ? e3 : (__expf(e3) - 1.f);
        hsm[ra][nh * 64 + 4 * j + tig]     = pkhf(e0, e1);
        hsm[ra + 8][nh * 64 + 4 * j + tig] = pkhf(e2, e3);
    }
    __syncthreads();

    // ---- Layer 2 ----
    float out[8][4];
    #pragma unroll
    for (int j = 0; j < 8; j++)
        #pragma unroll
        for (int e = 0; e < 4; e++) out[j][e] = 0.f;

    {
        const u32* wb = g_w2p + mlp * (128 * 128);
        #pragma unroll
        for (int ks = 0; ks < 16; ks++) {
            u32 a[4];
            a[0] = hsm[ra][8 * ks + tig];
            a[1] = hsm[ra + 8][8 * ks + tig];
            a[2] = hsm[ra][8 * ks + tig + 4];
            a[3] = hsm[ra + 8][8 * ks + tig + 4];
            #pragma unroll
            for (int j = 0; j < 8; j++) {
                const int n = nh * 64 + j * 8 + gID;
                const u32 b0 = __ldg(&wb[n * 128 + 8 * ks + tig]);
                const u32 b1 = __ldg(&wb[n * 128 + 8 * ks + tig + 4]);
                mma_f16(out[j], a, b0, b1);
            }
        }
    }

    // ---- epilogue: bias, scale(Q: 0.25*log2e), cvt fp16, scatter ----
    const float qsc = (mlp == 0) ? 0.25f * 1.4426950408889634f : 1.0f;
    #pragma unroll
    for (int j = 0; j < 8; j++) {
        const int c0 = nh * 64 + j * 8 + 2 * tig;
        const float bb0 = b2v[c0], bb1 = b2v[c0 + 1];
        const float v00 = (out[j][0] + bb0) * qsc;
        const float v01 = (out[j][1] + bb1) * qsc;
        const float v10 = (out[j][2] + bb0) * qsc;
        const float v11 = (out[j][3] + bb1) * qsc;
        const u32 pr = pkhf(v00, v01);
        const u32 ps = pkhf(v10, v11);

        const int h   = c0 >> 4;
        const int dk0 = c0 & 15;
        const int tokA = tok0 + ra;
        const int bA = tokA >> 11, sA = tokA & (S_ - 1);
        const int tokB = tokA + 8;
        const int bB = tokB >> 11, sB = tokB & (S_ - 1);
        const int bhA = bA * H_ + h, bhB = bB * H_ + h;

        if (mlp < 2) {
            u16* base = (mlp == 0) ? g_qs : g_ks;
            *(u32*)&base[((size_t)bhA * S_ + sA) * 16 + dk0] = pr;
            *(u32*)&base[((size_t)bhB * S_ + sB) * 16 + dk0] = ps;
        } else {
            g_vt[((size_t)bhA * 16 + dk0) * S_ + sA]     = (u16)(pr & 0xFFFF);
            g_vt[((size_t)bhA * 16 + dk0 + 1) * S_ + sA] = (u16)(pr >> 16);
            g_vt[((size_t)bhB * 16 + dk0) * S_ + sB]     = (u16)(ps & 0xFFFF);
            g_vt[((size_t)bhB * 16 + dk0 + 1) * S_ + sB] = (u16)(ps >> 16);
        }
    }
}

#define QSTR 24    // u16 per Q/K smem row -> 48B stride, fragment LDS bank-clean
#define VSTR 136   // u16 per Vt row -> 272B stride, bank-clean
#define ONES 0x3C003C00u

// ============================================================
// fp16 mma.sync flash attention, log2-domain scores, ex2.f16x2 softmax,
// lsum via ones-MMA. grid (S/64, B*H), 128 threads = 4 warps x 16 q rows.
// ============================================================
__global__ void __launch_bounds__(128) attn_mma_kernel()
{
    __shared__ __align__(16) u16 Qs[64][QSTR];     // 3072 B
    __shared__ __align__(16) u16 Ks[128][QSTR];    // 6144 B (reused as red[64][17])
    __shared__ __align__(16) u16 Vt[16][VSTR];     // 4352 B

    const int tid  = threadIdx.x;
    const int lane = tid & 31;
    const int warp = tid >> 5;
    const int gID  = lane >> 2;
    const int tig  = lane & 3;
    const int bh   = blockIdx.y;
    const int q0   = blockIdx.x * 64;

    // ---- Q tile: 64 rows x 2 uint4 ----
    {
        const int r    = tid >> 1;
        const int part = tid & 1;
        const uint4 v = *(const uint4*)&g_qs[((size_t)bh * S_ + q0 + r) * 16 + part * 8];
        *(uint4*)&Qs[r][part * 8] = v;
    }
    __syncthreads();

    u32 qa[4];
    const int ra = warp * 16 + gID;
    qa[0] = *(const u32*)&Qs[ra][2 * tig];
    qa[1] = *(const u32*)&Qs[ra + 8][2 * tig];
    qa[2] = *(const u32*)&Qs[ra][2 * tig + 8];
    qa[3] = *(const u32*)&Qs[ra + 8][2 * tig + 8];

    float out0[4] = {0.f, 0.f, 0.f, 0.f};
    float out1[4] = {0.f, 0.f, 0.f, 0.f};
    float ls[4]   = {0.f, 0.f, 0.f, 0.f};

    for (int t = 0; t < S_ / 128; t++) {
        __syncthreads();
        // ---- K tile: 128 rows x 2 uint4 = 256 loads / 128 threads ----
        #pragma unroll
        for (int cc = 0; cc < 2; cc++) {
            const int c    = tid + cc * 128;
            const int r    = c >> 1;
            const int part = c & 1;
            const uint4 v = *(const uint4*)&g_ks[((size_t)bh * S_ + t * 128 + r) * 16 + part * 8];
            *(uint4*)&Ks[r][part * 8] = v;
        }
        // ---- V tile: 16 rows x 16 uint4 = 256 loads ----
        #pragma unroll
        for (int cc = 0; cc < 2; cc++) {
            const int c   = tid + cc * 128;
            const int dk  = c >> 4;
            const int off = c & 15;
            const size_t gi = ((size_t)bh * 16 + dk) * S_ + t * 128 + off * 8;
            *(uint4*)&Vt[dk][off * 8] = *(const uint4*)&g_vt[gi];
        }
        __syncthreads();

        #pragma unroll
        for (int half = 0; half < 2; half++) {
            u32 pa[8], pb[8];

            // ---- scores (log2 domain) -> packed exp2 ----
            #pragma unroll
            for (int j = 0; j < 8; j++) {
                const int kn = half * 64 + j * 8 + gID;
                const u32 b0 = *(const u32*)&Ks[kn][2 * tig];
                const u32 b1 = *(const u32*)&Ks[kn][2 * tig + 8];
                float d[4] = {0.f, 0.f, 0.f, 0.f};
                mma_f16(d, qa, b0, b1);
                pa[j] = ex2h2(pkhf(d[0], d[1]));
                pb[j] = ex2h2(pkhf(d[2], d[3]));
            }

            // ---- PV + lsum mma ----
            #pragma unroll
            for (int ks = 0; ks < 4; ks++) {
                const u32 A[4] = {pa[2 * ks], pb[2 * ks], pa[2 * ks + 1], pb[2 * ks + 1]};
                const int kb2 = half * 64 + ks * 16 + 2 * tig;
                {
                    const u32 v0 = *(const u32*)&Vt[gID][kb2];
                    const u32 v1 = *(const u32*)&Vt[gID][kb2 + 8];
                    mma_f16(out0, A, v0, v1);
                }
                {
                    const u32 v0 = *(const u32*)&Vt[8 + gID][kb2];
                    const u32 v1 = *(const u32*)&Vt[8 + gID][kb2 + 8];
                    mma_f16(out1, A, v0, v1);
                }
                mma_f16(ls, A, ONES, ONES);
            }
        }
    }

    // ls[0] = full row sum (row ra), ls[2] = row ra+8 (exact, via tensor core)
    const float i0 = 1.f / ls[0];
    const float i1 = 1.f / ls[2];

    __syncthreads();                       // all warps done reading Ks/Vt
    float* red = (float*)&Ks[0][0];        // [64][17]
    {
        const int c0 = 2 * tig;
        red[ra * 17 + c0 + 0]       = out0[0] * i0;
        red[ra * 17 + c0 + 1]       = out0[1] * i0;
        red[(ra + 8) * 17 + c0 + 0] = out0[2] * i1;
        red[(ra + 8) * 17 + c0 + 1] = out0[3] * i1;
        red[ra * 17 + 8 + c0 + 0]       = out1[0] * i0;
        red[ra * 17 + 8 + c0 + 1]       = out1[1] * i0;
        red[(ra + 8) * 17 + 8 + c0 + 0] = out1[2] * i1;
        red[(ra + 8) * 17 + 8 + c0 + 1] = out1[3] * i1;
    }
    __syncthreads();

    float* part = (float*)&Qs[0][0];       // [8][16]
    {
        const int c  = tid & 15;
        const int r0 = tid >> 4;           // 0..7
        float m = red[r0 * 17 + c];
        #pragma unroll
        for (int i = 1; i < 8; i++)
            m = fmaxf(m, red[(r0 + 8 * i) * 17 + c]);
        part[r0 * 16 + c] = m;
    }
    __syncthreads();
    if (tid < 16) {
        float m = part[tid];
        #pragma unroll
        for (int r = 1; r < 8; r++)
            m = fmaxf(m, part[r * 16 + tid]);
        const int b = bh >> 3, h = bh & 7;
        atomicMax(&g_max[b * D_ + h * DK_ + tid], fkey(m));
    }
}

extern "C" void kernel_launch(void* const* d_in, const int* in_sizes, int n_in,
                              void* d_out, int out_size)
{
    const float* x   = (const float*)d_in[0];
    const float* qW1 = (const float*)d_in[1];
    const float* qb1 = (const float*)d_in[2];
    const float* qW2 = (const float*)d_in[3];
    const float* qb2 = (const float*)d_in[4];
    const float* kW1 = (const float*)d_in[5];
    const float* kb1 = (const float*)d_in[6];
    const float* kW2 = (const float*)d_in[7];
    const float* kb2 = (const float*)d_in[8];
    const float* vW1 = (const float*)d_in[9];
    const float* vb1 = (const float*)d_in[10];
    const float* vW2 = (const float*)d_in[11];
    const float* vb2 = (const float*)d_in[12];

    pack_weights_kernel<<<192, 256>>>(qW1, kW1, vW1, qW2, kW2, vW2);

    dim3 gmlp(B_ * S_ / 64, 3);
    mlp_mma_kernel<<<gmlp, 256>>>(x, qb1, qb2, kb1, kb2, vb1, vb2);

    dim3 gatt(S_ / 64, B_ * H_);
    attn_mma_kernel<<<gatt, 128>>>();

    finalize_kernel<<<1, B_ * D_>>>((float*)d_out);
}